// round 1
// baseline (speedup 1.0000x reference)
#include <cuda_runtime.h>
#include <math.h>

// ---------------------------------------------------------------------------
// Problem constants
//   outputs/styles: [4, 3, 256, 256] fp32
//   VGG16 features up to conv3_3, feats = concat(f1,f2,f3) -> [4, 768, 64, 64]
//   loss = mean over (b, n) of (1 - max_m  xn[b,n]·sn[b,m]),  C = 768, N = M = 4096
// ---------------------------------------------------------------------------

#define BATCH 4
#define FEATC 768
#define FEATN 4096   // 64*64 spatial locations

// Scratch (device globals; allocation is forbidden)
__device__ float g_bufA[(size_t)BATCH * 64 * 256 * 256];   // 16.78M floats
__device__ float g_bufB[(size_t)BATCH * 64 * 256 * 256];
__device__ float g_xfeat[(size_t)BATCH * FEATC * FEATN];   // 12.58M floats
__device__ float g_sfeat[(size_t)BATCH * FEATC * FEATN];
__device__ float g_maxsim[BATCH * FEATN];

// ---------------------------------------------------------------------------
// Input normalization: (x - mean[c]) / std[c]
// ---------------------------------------------------------------------------
__global__ void norm_input_kernel(const float* __restrict__ in, float* __restrict__ out,
                                  int total, int HW) {
    int i = blockIdx.x * blockDim.x + threadIdx.x;
    if (i >= total) return;
    int c = (i / HW) % 3;
    const float mean[3] = {0.485f, 0.456f, 0.406f};
    const float stdv[3] = {0.229f, 0.224f, 0.225f};
    out[i] = (in[i] - mean[c]) / stdv[c];
}

// ---------------------------------------------------------------------------
// 3x3 conv, stride 1, pad 1, + bias + ReLU.
// Block: 256 threads -> 32x32 spatial tile, 8 output channels.
// Each thread: 4 pixels x 8 oc accumulators. Input chunked 8 ic at a time in smem.
// ---------------------------------------------------------------------------
#define CTX 32
#define CTY 32

__global__ __launch_bounds__(256)
void conv3x3_relu_kernel(const float* __restrict__ in, const float* __restrict__ wgt,
                         const float* __restrict__ bias, float* __restrict__ out,
                         int Cin, int H, int W, long inBStride, long outBStride) {
    __shared__ float sIn[8][CTY + 2][CTX + 2];   // 8*34*34 = 9248 floats
    __shared__ float sW[8][8][9];                // [oc][ic][tap]

    const int b   = blockIdx.z;
    const int ocg = blockIdx.y;                  // group of 8 output channels
    const int tilesX = W / CTX;
    const int tx0 = (blockIdx.x % tilesX) * CTX;
    const int ty0 = (blockIdx.x / tilesX) * CTY;
    const int tid = threadIdx.x;
    const int lx = tid & 15;
    const int ly = tid >> 4;

    float acc[4][8];
#pragma unroll
    for (int i = 0; i < 4; i++)
#pragma unroll
        for (int j = 0; j < 8; j++) acc[i][j] = 0.f;

    const float* inB = in + (long)b * inBStride;
    const long HW = (long)H * W;

    for (int ic0 = 0; ic0 < Cin; ic0 += 8) {
        // cooperative load of input patch (zero-padded halo + tail channels)
        const int patchElems = 8 * (CTY + 2) * (CTX + 2);
        for (int i = tid; i < patchElems; i += 256) {
            int c = i / ((CTY + 2) * (CTX + 2));
            int r = i - c * ((CTY + 2) * (CTX + 2));
            int py = r / (CTX + 2);
            int px = r - py * (CTX + 2);
            int gy = ty0 + py - 1, gx = tx0 + px - 1;
            int ic = ic0 + c;
            float v = 0.f;
            if (ic < Cin && (unsigned)gy < (unsigned)H && (unsigned)gx < (unsigned)W)
                v = inB[(long)ic * HW + (long)gy * W + gx];
            sIn[c][py][px] = v;
        }
        // weights: 8 oc x 8 ic x 9 taps
        for (int i = tid; i < 8 * 8 * 9; i += 256) {
            int oc = i / 72;
            int r  = i - oc * 72;
            int ic = r / 9;
            int tap = r - ic * 9;
            float v = 0.f;
            if (ic0 + ic < Cin)
                v = wgt[((long)(ocg * 8 + oc) * Cin + (ic0 + ic)) * 9 + tap];
            sW[oc][ic][tap] = v;
        }
        __syncthreads();

#pragma unroll
        for (int ic = 0; ic < 8; ic++) {
#pragma unroll
            for (int t = 0; t < 9; t++) {
                const int ky = t / 3, kx = t - 3 * (t / 3);
                float v0 = sIn[ic][ly + ky][lx + kx];
                float v1 = sIn[ic][ly + ky][lx + 16 + kx];
                float v2 = sIn[ic][ly + 16 + ky][lx + kx];
                float v3 = sIn[ic][ly + 16 + ky][lx + 16 + kx];
#pragma unroll
                for (int oc = 0; oc < 8; oc++) {
                    float wv = sW[oc][ic][t];
                    acc[0][oc] = fmaf(v0, wv, acc[0][oc]);
                    acc[1][oc] = fmaf(v1, wv, acc[1][oc]);
                    acc[2][oc] = fmaf(v2, wv, acc[2][oc]);
                    acc[3][oc] = fmaf(v3, wv, acc[3][oc]);
                }
            }
        }
        __syncthreads();
    }

#pragma unroll
    for (int oc = 0; oc < 8; oc++) {
        int goc = ocg * 8 + oc;
        float bv = bias[goc];
        float* o = out + (long)b * outBStride + (long)goc * HW;
        o[(long)(ty0 + ly) * W + tx0 + lx]           = fmaxf(acc[0][oc] + bv, 0.f);
        o[(long)(ty0 + ly) * W + tx0 + lx + 16]      = fmaxf(acc[1][oc] + bv, 0.f);
        o[(long)(ty0 + ly + 16) * W + tx0 + lx]      = fmaxf(acc[2][oc] + bv, 0.f);
        o[(long)(ty0 + ly + 16) * W + tx0 + lx + 16] = fmaxf(acc[3][oc] + bv, 0.f);
    }
}

// ---------------------------------------------------------------------------
// 2x2 maxpool, stride 2
// ---------------------------------------------------------------------------
__global__ void maxpool2_kernel(const float* __restrict__ in, float* __restrict__ out,
                                int C, int H, int W, int B) {
    int Ho = H / 2, Wo = W / 2;
    long total = (long)B * C * Ho * Wo;
    long i = (long)blockIdx.x * blockDim.x + threadIdx.x;
    if (i >= total) return;
    int x = (int)(i % Wo);
    long t = i / Wo;
    int y = (int)(t % Ho); t /= Ho;
    int c = (int)(t % C);
    int b = (int)(t / C);
    const float* p = in + (((long)b * C + c) * H + 2 * y) * W + 2 * x;
    out[i] = fmaxf(fmaxf(p[0], p[1]), fmaxf(p[W], p[W + 1]));
}

// ---------------------------------------------------------------------------
// Per-spatial-location L2 normalization (in place, layout [B][C][N], C=768, N=4096)
// One thread per (b, n): coalesced across n.
// ---------------------------------------------------------------------------
__global__ void rownorm_kernel(float* __restrict__ f) {
    int t = blockIdx.x * blockDim.x + threadIdx.x;   // 16384 threads
    int b = t >> 12;
    int n = t & 4095;
    float* base = f + (long)b * FEATC * FEATN + n;
    float ssq = 0.f;
#pragma unroll 4
    for (int c = 0; c < FEATC; c++) {
        float v = base[(long)c * FEATN];
        ssq = fmaf(v, v, ssq);
    }
    float inv = 1.0f / (sqrtf(ssq) + 1e-8f);
#pragma unroll 4
    for (int c = 0; c < FEATC; c++)
        base[(long)c * FEATN] *= inv;
}

__global__ void initmax_kernel(float* __restrict__ g) {
    int i = blockIdx.x * blockDim.x + threadIdx.x;
    if (i < BATCH * FEATN) g[i] = 0.f;
}

// ---------------------------------------------------------------------------
// Similarity + row-max: per batch, 64x64 tile of [N, M], K=768 in chunks of 16.
// Thread microtile 4x4; warp-shuffle max over the m dimension; atomicMax merge.
// All cosines are >= 0 (ReLU features), so int-aliased atomicMax is order-correct.
// ---------------------------------------------------------------------------
__global__ __launch_bounds__(256)
void simmax_kernel(const float* __restrict__ xn, const float* __restrict__ sn,
                   float* __restrict__ gmax) {
    __shared__ float sX[16][64];
    __shared__ float sS[16][64];
    const int b = blockIdx.z;
    const int nbase = blockIdx.y * 64;
    const int mbase = blockIdx.x * 64;
    const int tid = threadIdx.x;
    const int txm = tid & 15;    // m sub-index (x4)
    const int tyn = tid >> 4;    // n sub-index (x4)
    const long CN = (long)FEATC * FEATN;
    const float* xb = xn + (long)b * CN;
    const float* sb = sn + (long)b * CN;

    float acc[4][4];
#pragma unroll
    for (int i = 0; i < 4; i++)
#pragma unroll
        for (int j = 0; j < 4; j++) acc[i][j] = 0.f;

    const int lk = tid >> 4;          // 0..15  (k row to load)
    const int lc = (tid & 15) * 4;    // 0..60  (column quad)

    for (int kc = 0; kc < FEATC; kc += 16) {
        float4 vx = *(const float4*)(xb + (long)(kc + lk) * FEATN + nbase + lc);
        float4 vs = *(const float4*)(sb + (long)(kc + lk) * FEATN + mbase + lc);
        *(float4*)&sX[lk][lc] = vx;
        *(float4*)&sS[lk][lc] = vs;
        __syncthreads();
#pragma unroll
        for (int k = 0; k < 16; k++) {
            float4 a  = *(const float4*)&sX[k][tyn * 4];
            float4 bb = *(const float4*)&sS[k][txm * 4];
            acc[0][0] = fmaf(a.x, bb.x, acc[0][0]);
            acc[0][1] = fmaf(a.x, bb.y, acc[0][1]);
            acc[0][2] = fmaf(a.x, bb.z, acc[0][2]);
            acc[0][3] = fmaf(a.x, bb.w, acc[0][3]);
            acc[1][0] = fmaf(a.y, bb.x, acc[1][0]);
            acc[1][1] = fmaf(a.y, bb.y, acc[1][1]);
            acc[1][2] = fmaf(a.y, bb.z, acc[1][2]);
            acc[1][3] = fmaf(a.y, bb.w, acc[1][3]);
            acc[2][0] = fmaf(a.z, bb.x, acc[2][0]);
            acc[2][1] = fmaf(a.z, bb.y, acc[2][1]);
            acc[2][2] = fmaf(a.z, bb.z, acc[2][2]);
            acc[2][3] = fmaf(a.z, bb.w, acc[2][3]);
            acc[3][0] = fmaf(a.w, bb.x, acc[3][0]);
            acc[3][1] = fmaf(a.w, bb.y, acc[3][1]);
            acc[3][2] = fmaf(a.w, bb.z, acc[3][2]);
            acc[3][3] = fmaf(a.w, bb.w, acc[3][3]);
        }
        __syncthreads();
    }

#pragma unroll
    for (int i = 0; i < 4; i++) {
        float m = fmaxf(fmaxf(acc[i][0], acc[i][1]), fmaxf(acc[i][2], acc[i][3]));
        // reduce max across the 16 threads that share tyn (tid bits 0..3)
        m = fmaxf(m, __shfl_xor_sync(0xffffffff, m, 1));
        m = fmaxf(m, __shfl_xor_sync(0xffffffff, m, 2));
        m = fmaxf(m, __shfl_xor_sync(0xffffffff, m, 4));
        m = fmaxf(m, __shfl_xor_sync(0xffffffff, m, 8));
        if (txm == 0)
            atomicMax((int*)&gmax[(long)b * FEATN + nbase + tyn * 4 + i],
                      __float_as_int(m));
    }
}

// ---------------------------------------------------------------------------
// Final reduction: mean(1 - maxsim)
// ---------------------------------------------------------------------------
__global__ void final_loss_kernel(const float* __restrict__ gmax, float* __restrict__ out) {
    __shared__ double sm[256];
    double s = 0.0;
    for (int i = threadIdx.x; i < BATCH * FEATN; i += 256)
        s += 1.0 - (double)gmax[i];
    sm[threadIdx.x] = s;
    __syncthreads();
    for (int st = 128; st > 0; st >>= 1) {
        if (threadIdx.x < st) sm[threadIdx.x] += sm[threadIdx.x + st];
        __syncthreads();
    }
    if (threadIdx.x == 0)
        out[0] = (float)(sm[0] / (double)(BATCH * FEATN));
}

// ---------------------------------------------------------------------------
// Host orchestration
// ---------------------------------------------------------------------------
static void run_vgg_stack(const float* img, void* const* d_in,
                          float* bufA, float* bufB, float* feat) {
    const float* w[7];
    const float* bs[7];
    for (int i = 0; i < 7; i++) {
        w[i]  = (const float*)d_in[2 + 2 * i];
        bs[i] = (const float*)d_in[3 + 2 * i];
    }

    // normalize input -> bufA  [4,3,256,256]
    norm_input_kernel<<<(BATCH * 3 * 256 * 256 + 255) / 256, 256>>>(
        img, bufA, BATCH * 3 * 256 * 256, 256 * 256);

    // conv1_1: 3 -> 64 @256    A -> B
    conv3x3_relu_kernel<<<dim3(64, 8, BATCH), 256>>>(
        bufA, w[0], bs[0], bufB, 3, 256, 256, 3L * 65536, 64L * 65536);
    // conv1_2: 64 -> 64 @256   B -> A
    conv3x3_relu_kernel<<<dim3(64, 8, BATCH), 256>>>(
        bufB, w[1], bs[1], bufA, 64, 256, 256, 64L * 65536, 64L * 65536);
    // pool: A[4,64,256,256] -> B[4,64,128,128]
    {
        long total = (long)BATCH * 64 * 128 * 128;
        maxpool2_kernel<<<(unsigned)((total + 255) / 256), 256>>>(bufA, bufB, 64, 256, 256, BATCH);
    }
    // conv2_1: 64 -> 128 @128  B -> A
    conv3x3_relu_kernel<<<dim3(16, 16, BATCH), 256>>>(
        bufB, w[2], bs[2], bufA, 64, 128, 128, 64L * 16384, 128L * 16384);
    // conv2_2: 128 -> 128 @128 A -> B
    conv3x3_relu_kernel<<<dim3(16, 16, BATCH), 256>>>(
        bufA, w[3], bs[3], bufB, 128, 128, 128, 128L * 16384, 128L * 16384);
    // pool: B[4,128,128,128] -> A[4,128,64,64]
    {
        long total = (long)BATCH * 128 * 64 * 64;
        maxpool2_kernel<<<(unsigned)((total + 255) / 256), 256>>>(bufB, bufA, 128, 128, 128, BATCH);
    }
    // conv3_1: 128 -> 256 @64  A -> feat[:, 0:256]
    conv3x3_relu_kernel<<<dim3(4, 32, BATCH), 256>>>(
        bufA, w[4], bs[4], feat, 128, 64, 64, 128L * 4096, (long)FEATC * 4096);
    // conv3_2: 256 -> 256 @64  feat[:,0:256] -> feat[:, 256:512]
    conv3x3_relu_kernel<<<dim3(4, 32, BATCH), 256>>>(
        feat, w[5], bs[5], feat + 256L * 4096, 256, 64, 64,
        (long)FEATC * 4096, (long)FEATC * 4096);
    // conv3_3: 256 -> 256 @64  feat[:,256:512] -> feat[:, 512:768]
    conv3x3_relu_kernel<<<dim3(4, 32, BATCH), 256>>>(
        feat + 256L * 4096, w[6], bs[6], feat + 512L * 4096, 256, 64, 64,
        (long)FEATC * 4096, (long)FEATC * 4096);
}

extern "C" void kernel_launch(void* const* d_in, const int* in_sizes, int n_in,
                              void* d_out, int out_size) {
    (void)in_sizes; (void)n_in; (void)out_size;

    float *bufA, *bufB, *xfeat, *sfeat, *gmax;
    cudaGetSymbolAddress((void**)&bufA,  g_bufA);
    cudaGetSymbolAddress((void**)&bufB,  g_bufB);
    cudaGetSymbolAddress((void**)&xfeat, g_xfeat);
    cudaGetSymbolAddress((void**)&sfeat, g_sfeat);
    cudaGetSymbolAddress((void**)&gmax,  g_maxsim);

    const float* outputs = (const float*)d_in[0];
    const float* styles  = (const float*)d_in[1];

    run_vgg_stack(outputs, d_in, bufA, bufB, xfeat);
    run_vgg_stack(styles,  d_in, bufA, bufB, sfeat);

    rownorm_kernel<<<64, 256>>>(xfeat);
    rownorm_kernel<<<64, 256>>>(sfeat);

    initmax_kernel<<<(BATCH * FEATN + 255) / 256, 256>>>(gmax);

    simmax_kernel<<<dim3(64, 64, BATCH), 256>>>(xfeat, sfeat, gmax);

    final_loss_kernel<<<1, 256>>>(gmax, (float*)d_out);
}

// round 3
// speedup vs baseline: 1.3574x; 1.3574x over previous
#include <cuda_runtime.h>
#include <cstdint>
#include <math.h>

// ---------------------------------------------------------------------------
// Problem: VGG16-block3 features on outputs+styles [4,3,256,256], then
// loss = mean_{b,n} (1 - max_m  xn[b,n] . sn[b,m]),  C=768, N=M=4096.
// ---------------------------------------------------------------------------

#define BATCH 4
#define FEATC 768
#define FEATN 4096

__device__ float g_bufA[(size_t)BATCH * 64 * 256 * 256];
__device__ float g_bufB[(size_t)BATCH * 64 * 256 * 256];
__device__ float g_xfeat[(size_t)BATCH * FEATC * FEATN];
__device__ float g_sfeat[(size_t)BATCH * FEATC * FEATN];
__device__ float g_inv[BATCH * FEATN];
__device__ float g_maxsim[BATCH * FEATN];

// packed dual-FMA (FFMA2) — sm_10x 2x fp32 path, only reachable via PTX
typedef unsigned long long u64t;
#define FFMA2(d, a, b, c) \
    asm("fma.rn.f32x2 %0, %1, %2, %3;" : "=l"(d) : "l"(a), "l"(b), "l"(c))
#define PACK2(out, x) do { uint32_t _u = __float_as_uint(x); \
    asm("mov.b64 %0, {%1, %1};" : "=l"(out) : "r"(_u)); } while (0)
#define UNPACK2(lo, hi, in) do { uint32_t _a, _b; \
    asm("mov.b64 {%0, %1}, %2;" : "=r"(_a), "=r"(_b) : "l"(in)); \
    lo = __uint_as_float(_a); hi = __uint_as_float(_b); } while (0)

__device__ __forceinline__ uint32_t tf32r(float x) {
    uint32_t y;
    asm("cvt.rna.tf32.f32 %0, %1;" : "=r"(y) : "f"(x));
    return y;
}

// ---------------------------------------------------------------------------
// Input normalization
// ---------------------------------------------------------------------------
__global__ void norm_input_kernel(const float* __restrict__ in, float* __restrict__ out,
                                  int total, int HW) {
    int i = blockIdx.x * blockDim.x + threadIdx.x;
    if (i >= total) return;
    int c = (i / HW) % 3;
    const float mean[3] = {0.485f, 0.456f, 0.406f};
    const float stdv[3] = {0.229f, 0.224f, 0.225f};
    out[i] = (in[i] - mean[c]) / stdv[c];
}

// ---------------------------------------------------------------------------
// 3x3 conv + bias + ReLU, FFMA2 inner loop.
// 256 threads -> 32x32 spatial tile x 8 oc; thread = 4 px x 4 oc-pairs.
// ---------------------------------------------------------------------------
__global__ __launch_bounds__(256)
void conv3x3_relu_kernel(const float* __restrict__ in, const float* __restrict__ wgt,
                         const float* __restrict__ bias, float* __restrict__ out,
                         int Cin, int H, int W, long inBStride, long outBStride) {
    __shared__ float sIn[8][34][34];
    __shared__ float sW2[8][9][8];   // [ic][tap][oc]

    const int b   = blockIdx.z;
    const int ocg = blockIdx.y;
    const int tilesX = W / 32;
    const int tx0 = (blockIdx.x % tilesX) * 32;
    const int ty0 = (blockIdx.x / tilesX) * 32;
    const int tid = threadIdx.x;
    const int lx = tid & 15;
    const int ly = tid >> 4;

    u64t acc2[4][4];
#pragma unroll
    for (int i = 0; i < 4; i++)
#pragma unroll
        for (int j = 0; j < 4; j++) acc2[i][j] = 0ULL;

    const float* inB = in + (long)b * inBStride;
    const long HW = (long)H * W;

    for (int ic0 = 0; ic0 < Cin; ic0 += 8) {
        for (int i = tid; i < 8 * 34 * 34; i += 256) {
            int c = i / (34 * 34);
            int r = i - c * (34 * 34);
            int py = r / 34, px = r - py * 34;
            int gy = ty0 + py - 1, gx = tx0 + px - 1;
            int ic = ic0 + c;
            float v = 0.f;
            if (ic < Cin && (unsigned)gy < (unsigned)H && (unsigned)gx < (unsigned)W)
                v = inB[(long)ic * HW + (long)gy * W + gx];
            sIn[c][py][px] = v;
        }
        for (int i = tid; i < 8 * 9 * 8; i += 256) {
            int ic = i / 72;
            int r = i - ic * 72;
            int tap = r >> 3, oc = r & 7;
            float v = 0.f;
            if (ic0 + ic < Cin)
                v = wgt[((long)(ocg * 8 + oc) * Cin + (ic0 + ic)) * 9 + tap];
            sW2[ic][tap][oc] = v;
        }
        __syncthreads();

#pragma unroll
        for (int ic = 0; ic < 8; ic++) {
#pragma unroll
            for (int t = 0; t < 9; t++) {
                const int ky = t / 3, kx = t - 3 * (t / 3);
                float v0 = sIn[ic][ly + ky][lx + kx];
                float v1 = sIn[ic][ly + ky][lx + 16 + kx];
                float v2 = sIn[ic][ly + 16 + ky][lx + kx];
                float v3 = sIn[ic][ly + 16 + ky][lx + 16 + kx];
                u64t vv0, vv1, vv2, vv3;
                PACK2(vv0, v0); PACK2(vv1, v1); PACK2(vv2, v2); PACK2(vv3, v3);
                const u64t* wp = (const u64t*)&sW2[ic][t][0];
#pragma unroll
                for (int j = 0; j < 4; j++) {
                    u64t w2 = wp[j];
                    FFMA2(acc2[0][j], vv0, w2, acc2[0][j]);
                    FFMA2(acc2[1][j], vv1, w2, acc2[1][j]);
                    FFMA2(acc2[2][j], vv2, w2, acc2[2][j]);
                    FFMA2(acc2[3][j], vv3, w2, acc2[3][j]);
                }
            }
        }
        __syncthreads();
    }

#pragma unroll
    for (int j = 0; j < 4; j++) {
        int goc0 = ocg * 8 + 2 * j;
        float bv0 = bias[goc0], bv1 = bias[goc0 + 1];
        float* o0 = out + (long)b * outBStride + (long)goc0 * HW;
        float* o1 = o0 + HW;
#pragma unroll
        for (int i = 0; i < 4; i++) {
            float lo, hi;
            UNPACK2(lo, hi, acc2[i][j]);
            int yy = ty0 + ly + ((i >> 1) << 4);
            int xx = tx0 + lx + ((i & 1) << 4);
            o0[(long)yy * W + xx] = fmaxf(lo + bv0, 0.f);
            o1[(long)yy * W + xx] = fmaxf(hi + bv1, 0.f);
        }
    }
}

// ---------------------------------------------------------------------------
// 2x2 maxpool
// ---------------------------------------------------------------------------
__global__ void maxpool2_kernel(const float* __restrict__ in, float* __restrict__ out,
                                int C, int H, int W, int B) {
    int Ho = H / 2, Wo = W / 2;
    long total = (long)B * C * Ho * Wo;
    long i = (long)blockIdx.x * blockDim.x + threadIdx.x;
    if (i >= total) return;
    int x = (int)(i % Wo);
    long t = i / Wo;
    int y = (int)(t % Ho); t /= Ho;
    int c = (int)(t % C);
    int b = (int)(t / C);
    const float* p = in + (((long)b * C + c) * H + 2 * y) * W + 2 * x;
    out[i] = fmaxf(fmaxf(p[0], p[1]), fmaxf(p[W], p[W + 1]));
}

// ---------------------------------------------------------------------------
// inv-norm per (b, n) over channels; feat layout [B][C][N]
// ---------------------------------------------------------------------------
__global__ void invnorm_kernel(const float* __restrict__ f, float* __restrict__ inv) {
    int t = blockIdx.x * blockDim.x + threadIdx.x;
    int b = t >> 12, n = t & 4095;
    const float* base = f + (long)b * FEATC * FEATN + n;
    float ssq = 0.f;
#pragma unroll 4
    for (int c = 0; c < FEATC; c++) {
        float v = base[(long)c * FEATN];
        ssq = fmaf(v, v, ssq);
    }
    inv[t] = 1.0f / (sqrtf(ssq) + 1e-8f);
}

// ---------------------------------------------------------------------------
// transpose+scale: [B][C][N] -> [B][N][C] with per-n scale
// ---------------------------------------------------------------------------
__global__ void transpose_scale_kernel(const float* __restrict__ f, const float* __restrict__ inv,
                                       float* __restrict__ out) {
    __shared__ float s[32][33];
    int b = blockIdx.z;
    int c0 = blockIdx.y * 32, n0 = blockIdx.x * 32;
    int tx = threadIdx.x, ty = threadIdx.y;   // 32 x 8
    const float* fb = f + (long)b * FEATC * FEATN;
#pragma unroll
    for (int i = 0; i < 4; i++)
        s[ty + 8 * i][tx] = fb[(long)(c0 + ty + 8 * i) * FEATN + n0 + tx];
    __syncthreads();
    float* ob = out + (long)b * FEATN * FEATC;
#pragma unroll
    for (int i = 0; i < 4; i++) {
        int n = n0 + ty + 8 * i;
        ob[(long)n * FEATC + c0 + tx] = s[tx][ty + 8 * i] * inv[b * FEATN + n];
    }
}

__global__ void initmax_kernel(float* __restrict__ g) {
    int i = blockIdx.x * blockDim.x + threadIdx.x;
    if (i < BATCH * FEATN) g[i] = 0.f;
}

// ---------------------------------------------------------------------------
// tf32 mma.sync sim + row-max.  Block tile 128x128, warp tile 64x32 (2x4 warps),
// K chunk 32.  Features in [B][N][C] row-major (A row-major, B "col"-major).
// ---------------------------------------------------------------------------
#define MMA_TF32(c, a, bfr) \
    asm volatile("mma.sync.aligned.m16n8k8.row.col.f32.tf32.tf32.f32 " \
        "{%0,%1,%2,%3}, {%4,%5,%6,%7}, {%8,%9}, {%0,%1,%2,%3};" \
        : "+f"((c)[0]), "+f"((c)[1]), "+f"((c)[2]), "+f"((c)[3]) \
        : "r"((a)[0]), "r"((a)[1]), "r"((a)[2]), "r"((a)[3]), \
          "r"((bfr)[0]), "r"((bfr)[1]))

__global__ __launch_bounds__(256)
void simmax_mma_kernel(const float* __restrict__ xT, const float* __restrict__ sT,
                       float* __restrict__ gmax) {
    __shared__ float As[128][36];
    __shared__ float Bs[128][36];

    const int b = blockIdx.z;
    const int nbase = blockIdx.y * 128;   // x rows (output rows we max over m)
    const int mbase = blockIdx.x * 128;   // style rows
    const int tid = threadIdx.x;
    const int wid = tid >> 5, lane = tid & 31;
    const int wm = wid & 1, wn = wid >> 1;
    const int grp = lane >> 2, tg = lane & 3;

    const float* xb = xT + ((long)b * FEATN + nbase) * FEATC;
    const float* sp = sT + ((long)b * FEATN + mbase) * FEATC;

    float acc[4][4][4];
#pragma unroll
    for (int mf = 0; mf < 4; mf++)
#pragma unroll
        for (int nf = 0; nf < 4; nf++)
#pragma unroll
            for (int k = 0; k < 4; k++) acc[mf][nf][k] = 0.f;

    for (int chunk = 0; chunk < FEATC / 32; chunk++) {
        const int kc = chunk * 32;
#pragma unroll
        for (int i = 0; i < 4; i++) {
            int id = tid + i * 256;           // 0..1023
            int r = id >> 3, q = (id & 7) * 4;
            float4 v = *(const float4*)(xb + (long)r * FEATC + kc + q);
            As[r][q + 0] = __uint_as_float(tf32r(v.x));
            As[r][q + 1] = __uint_as_float(tf32r(v.y));
            As[r][q + 2] = __uint_as_float(tf32r(v.z));
            As[r][q + 3] = __uint_as_float(tf32r(v.w));
            float4 w = *(const float4*)(sp + (long)r * FEATC + kc + q);
            Bs[r][q + 0] = __uint_as_float(tf32r(w.x));
            Bs[r][q + 1] = __uint_as_float(tf32r(w.y));
            Bs[r][q + 2] = __uint_as_float(tf32r(w.z));
            Bs[r][q + 3] = __uint_as_float(tf32r(w.w));
        }
        __syncthreads();

#pragma unroll
        for (int ks = 0; ks < 4; ks++) {
            const int kk = ks * 8;
            uint32_t a[4][4];
#pragma unroll
            for (int mf = 0; mf < 4; mf++) {
                int m0 = wm * 64 + mf * 16 + grp;
                a[mf][0] = __float_as_uint(As[m0][kk + tg]);
                a[mf][1] = __float_as_uint(As[m0 + 8][kk + tg]);
                a[mf][2] = __float_as_uint(As[m0][kk + tg + 4]);
                a[mf][3] = __float_as_uint(As[m0 + 8][kk + tg + 4]);
            }
            uint32_t bf[4][2];
#pragma unroll
            for (int nf = 0; nf < 4; nf++) {
                int n0 = wn * 32 + nf * 8 + grp;
                bf[nf][0] = __float_as_uint(Bs[n0][kk + tg]);
                bf[nf][1] = __float_as_uint(Bs[n0][kk + tg + 4]);
            }
#pragma unroll
            for (int mf = 0; mf < 4; mf++)
#pragma unroll
                for (int nf = 0; nf < 4; nf++)
                    MMA_TF32(acc[mf][nf], a[mf], bf[nf]);
        }
        __syncthreads();
    }

    // epilogue: row-max.  c0/c1 -> row grp, c2/c3 -> row grp+8 of each 16-row frag.
#pragma unroll
    for (int mf = 0; mf < 4; mf++) {
        float r0 = 0.f, r1 = 0.f;
#pragma unroll
        for (int nf = 0; nf < 4; nf++) {
            r0 = fmaxf(r0, fmaxf(acc[mf][nf][0], acc[mf][nf][1]));
            r1 = fmaxf(r1, fmaxf(acc[mf][nf][2], acc[mf][nf][3]));
        }
        r0 = fmaxf(r0, __shfl_xor_sync(0xffffffff, r0, 1));
        r0 = fmaxf(r0, __shfl_xor_sync(0xffffffff, r0, 2));
        r1 = fmaxf(r1, __shfl_xor_sync(0xffffffff, r1, 1));
        r1 = fmaxf(r1, __shfl_xor_sync(0xffffffff, r1, 2));
        if (tg == 0) {
            int row = nbase + wm * 64 + mf * 16 + grp;
            atomicMax((int*)&gmax[(long)b * FEATN + row], __float_as_int(r0));
            atomicMax((int*)&gmax[(long)b * FEATN + row + 8], __float_as_int(r1));
        }
    }
}

// ---------------------------------------------------------------------------
// Final reduction
// ---------------------------------------------------------------------------
__global__ void final_loss_kernel(const float* __restrict__ gmax, float* __restrict__ out) {
    __shared__ double sm[256];
    double s = 0.0;
    for (int i = threadIdx.x; i < BATCH * FEATN; i += 256)
        s += 1.0 - (double)gmax[i];
    sm[threadIdx.x] = s;
    __syncthreads();
    for (int st = 128; st > 0; st >>= 1) {
        if (threadIdx.x < st) sm[threadIdx.x] += sm[threadIdx.x + st];
        __syncthreads();
    }
    if (threadIdx.x == 0)
        out[0] = (float)(sm[0] / (double)(BATCH * FEATN));
}

// ---------------------------------------------------------------------------
// Host orchestration
// ---------------------------------------------------------------------------
static void run_vgg_stack(const float* img, void* const* d_in,
                          float* bufA, float* bufB, float* feat) {
    const float* w[7];
    const float* bs[7];
    for (int i = 0; i < 7; i++) {
        w[i]  = (const float*)d_in[2 + 2 * i];
        bs[i] = (const float*)d_in[3 + 2 * i];
    }
    norm_input_kernel<<<(BATCH * 3 * 256 * 256 + 255) / 256, 256>>>(
        img, bufA, BATCH * 3 * 256 * 256, 256 * 256);
    conv3x3_relu_kernel<<<dim3(64, 8, BATCH), 256>>>(
        bufA, w[0], bs[0], bufB, 3, 256, 256, 3L * 65536, 64L * 65536);
    conv3x3_relu_kernel<<<dim3(64, 8, BATCH), 256>>>(
        bufB, w[1], bs[1], bufA, 64, 256, 256, 64L * 65536, 64L * 65536);
    {
        long total = (long)BATCH * 64 * 128 * 128;
        maxpool2_kernel<<<(unsigned)((total + 255) / 256), 256>>>(bufA, bufB, 64, 256, 256, BATCH);
    }
    conv3x3_relu_kernel<<<dim3(16, 16, BATCH), 256>>>(
        bufB, w[2], bs[2], bufA, 64, 128, 128, 64L * 16384, 128L * 16384);
    conv3x3_relu_kernel<<<dim3(16, 16, BATCH), 256>>>(
        bufA, w[3], bs[3], bufB, 128, 128, 128, 128L * 16384, 128L * 16384);
    {
        long total = (long)BATCH * 128 * 64 * 64;
        maxpool2_kernel<<<(unsigned)((total + 255) / 256), 256>>>(bufB, bufA, 128, 128, 128, BATCH);
    }
    conv3x3_relu_kernel<<<dim3(4, 32, BATCH), 256>>>(
        bufA, w[4], bs[4], feat, 128, 64, 64, 128L * 4096, (long)FEATC * 4096);
    conv3x3_relu_kernel<<<dim3(4, 32, BATCH), 256>>>(
        feat, w[5], bs[5], feat + 256L * 4096, 256, 64, 64,
        (long)FEATC * 4096, (long)FEATC * 4096);
    conv3x3_relu_kernel<<<dim3(4, 32, BATCH), 256>>>(
        feat + 256L * 4096, w[6], bs[6], feat + 512L * 4096, 256, 64, 64,
        (long)FEATC * 4096, (long)FEATC * 4096);
}

extern "C" void kernel_launch(void* const* d_in, const int* in_sizes, int n_in,
                              void* d_out, int out_size) {
    (void)in_sizes; (void)n_in; (void)out_size;

    float *bufA, *bufB, *xfeat, *sfeat, *inv, *gmax;
    cudaGetSymbolAddress((void**)&bufA,  g_bufA);
    cudaGetSymbolAddress((void**)&bufB,  g_bufB);
    cudaGetSymbolAddress((void**)&xfeat, g_xfeat);
    cudaGetSymbolAddress((void**)&sfeat, g_sfeat);
    cudaGetSymbolAddress((void**)&inv,   g_inv);
    cudaGetSymbolAddress((void**)&gmax,  g_maxsim);

    const float* outputs = (const float*)d_in[0];
    const float* styles  = (const float*)d_in[1];

    run_vgg_stack(outputs, d_in, bufA, bufB, xfeat);
    run_vgg_stack(styles,  d_in, bufA, bufB, sfeat);

    // normalized transposed features: x -> bufA, s -> bufB
    invnorm_kernel<<<64, 256>>>(xfeat, inv);
    transpose_scale_kernel<<<dim3(128, 24, BATCH), dim3(32, 8)>>>(xfeat, inv, bufA);
    invnorm_kernel<<<64, 256>>>(sfeat, inv);
    transpose_scale_kernel<<<dim3(128, 24, BATCH), dim3(32, 8)>>>(sfeat, inv, bufB);

    initmax_kernel<<<(BATCH * FEATN + 255) / 256, 256>>>(gmax);

    simmax_mma_kernel<<<dim3(FEATN / 128, FEATN / 128, BATCH), 256>>>(bufA, bufB, gmax);

    final_loss_kernel<<<1, 256>>>(gmax, (float*)d_out);
}

// round 5
// speedup vs baseline: 1.5348x; 1.1307x over previous
#include <cuda_runtime.h>
#include <cstdint>
#include <math.h>

// ---------------------------------------------------------------------------
// VGG16-block3 features on outputs+styles [4,3,256,256], then
// loss = mean_{b,n} (1 - max_m xn[b,n].sn[b,m]),  C=768, N=M=4096.
// All activations kept in zero-padded [C][H+2][W+2] layout so 3x3 conv is
// 9 pointer-shifted tf32 MMA GEMMs with no boundary handling.
// ---------------------------------------------------------------------------

#define BATCH 4
#define FEATC 768
#define FEATN 4096

// Padded activation buffers (device globals; allocation is forbidden)
__device__ float g_pad0[(size_t)BATCH * 3 * 258 * 258];
__device__ float g_pad1[(size_t)BATCH * 64 * 258 * 258];
__device__ float g_pad2[(size_t)BATCH * 64 * 258 * 258];
__device__ float g_pad3[(size_t)BATCH * 64 * 130 * 130];
__device__ float g_pad4[(size_t)BATCH * 128 * 130 * 130];
__device__ float g_pad5[(size_t)BATCH * 128 * 130 * 130];
__device__ float g_pad6[(size_t)BATCH * 128 * 66 * 66];
__device__ float g_f1[(size_t)BATCH * 256 * 66 * 66];
__device__ float g_f2[(size_t)BATCH * 256 * 66 * 66];
__device__ float g_f3[(size_t)BATCH * 256 * 66 * 66];
__device__ float g_xT[(size_t)BATCH * FEATN * FEATC];
__device__ float g_sT[(size_t)BATCH * FEATN * FEATC];
__device__ float g_wT[1734336];
__device__ float g_maxsim[BATCH * FEATN];

__device__ __forceinline__ uint32_t tf32r(float x) {
    uint32_t y;
    asm("cvt.rna.tf32.f32 %0, %1;" : "=r"(y) : "f"(x));
    return y;
}

#define MMA_TF32(c, a, bfr) \
    asm volatile("mma.sync.aligned.m16n8k8.row.col.f32.tf32.tf32.f32 " \
        "{%0,%1,%2,%3}, {%4,%5,%6,%7}, {%8,%9}, {%0,%1,%2,%3};" \
        : "+f"((c)[0]), "+f"((c)[1]), "+f"((c)[2]), "+f"((c)[3]) \
        : "r"((a)[0]), "r"((a)[1]), "r"((a)[2]), "r"((a)[3]), \
          "r"((bfr)[0]), "r"((bfr)[1]))

// ---------------------------------------------------------------------------
// zero fill (grid-strided)
// ---------------------------------------------------------------------------
__global__ void zero_kernel(float* __restrict__ p, long n) {
    long stride = (long)gridDim.x * blockDim.x;
    for (long i = (long)blockIdx.x * blockDim.x + threadIdx.x; i < n; i += stride)
        p[i] = 0.f;
}

// ---------------------------------------------------------------------------
// input normalization -> padded layout
// ---------------------------------------------------------------------------
__global__ void norm_input_pad_kernel(const float* __restrict__ in, float* __restrict__ out) {
    int i = blockIdx.x * blockDim.x + threadIdx.x;
    if (i >= BATCH * 3 * 65536) return;
    int x = i & 255, y = (i >> 8) & 255;
    int c = (i >> 16) % 3, b = i / (3 * 65536);
    const float mean[3] = {0.485f, 0.456f, 0.406f};
    const float stdv[3] = {0.229f, 0.224f, 0.225f};
    out[((long)(b * 3 + c) * 258 + 1 + y) * 258 + 1 + x] = (in[i] - mean[c]) / stdv[c];
}

// ---------------------------------------------------------------------------
// weight transpose: w[oc][ic][tap] -> wT[(ic*9+tap)][oc]
// ---------------------------------------------------------------------------
__global__ void wtrans_kernel(const float* __restrict__ w, float* __restrict__ wT,
                              int OC, int Cin) {
    int total = OC * Cin * 9;
    int i = blockIdx.x * blockDim.x + threadIdx.x;
    if (i >= total) return;
    int oc = i % OC, r = i / OC;               // r = ic*9+tap
    wT[i] = w[(long)oc * Cin * 9 + r];
}

// ---------------------------------------------------------------------------
// tf32 implicit-GEMM 3x3 conv + bias + ReLU on padded buffers.
// Block: 256 thr, tile 64 oc x 128 px; warps 2(M) x 4(N) -> 32x32 each.
// K chunk = 16 ic; 9 taps x 2 ksteps of m16n8k8.
// R=1: tile = 128 px of one row (W>=128).  R=2: tile = 2 rows of 64 (W=64).
// ---------------------------------------------------------------------------
__global__ __launch_bounds__(256)
void conv_mma_kernel(const float* __restrict__ in_pad, const float* __restrict__ wT,
                     const float* __restrict__ bias, float* __restrict__ out_pad,
                     int Cin, int OC, int H, int W, int R) {
    extern __shared__ float smem[];
    float* Ws = smem;              // [16][9][72] = 10368 floats
    float* patch = smem + 10368;   // R1: [16][3][136]=6528, R2: [16][4][66]=4224

    const int tid = threadIdx.x;
    const int wid = tid >> 5, lane = tid & 31;
    const int wm = wid & 1, wn = wid >> 1;
    const int grp = lane >> 2, tg = lane & 3;

    const int b = blockIdx.z;
    const int ocg = blockIdx.y;
    const int tile = blockIdx.x;

    const int PW = W + 2;
    const long plane = (long)(H + 2) * PW;
    const int rowStride = (R == 1) ? 136 : 66;
    const int icStride  = (R == 1) ? 408 : 264;

    int ty = 0, x0 = 0, y0 = 0;
    if (R == 1) { int tpr = W >> 7; ty = tile / tpr; x0 = (tile - ty * tpr) << 7; }
    else        { y0 = tile << 1; }

    const float* inB = in_pad + (long)b * Cin * plane;

    int nb[4];
#pragma unroll
    for (int nf = 0; nf < 4; nf++) {
        int n = wn * 32 + nf * 8 + grp;
        nb[nf] = (R == 1) ? n : ((n >> 6) * 66 + (n & 63));
    }

    float acc[2][4][4];
#pragma unroll
    for (int mf = 0; mf < 2; mf++)
#pragma unroll
        for (int nf = 0; nf < 4; nf++)
#pragma unroll
            for (int k = 0; k < 4; k++) acc[mf][nf][k] = 0.f;

    for (int ic0 = 0; ic0 < Cin; ic0 += 16) {
        // weights: 16 ic x 9 taps x 64 oc (coalesced over oc)
        for (int id = tid; id < 9216; id += 256) {
            int ic = id / 576, r = id - ic * 576;
            int tap = r >> 6, oc = r & 63;
            float v = 0.f;
            if (ic0 + ic < Cin)
                v = wT[((long)(ic0 + ic) * 9 + tap) * OC + ocg * 64 + oc];
            Ws[(ic * 9 + tap) * 72 + oc] = __uint_as_float(tf32r(v));
        }
        // input patch (rows incl. halo), coalesced over x
        if (R == 1) {
            for (int rs = wid; rs < 48; rs += 8) {
                int ic = rs / 3, row = rs - 3 * ic;
                const float* src = (ic0 + ic < Cin)
                    ? inB + (long)(ic0 + ic) * plane + (long)(ty + row) * PW + x0 : nullptr;
                float* dst = patch + ic * 408 + row * 136;
                for (int x = lane; x < 130; x += 32)
                    dst[x] = __uint_as_float(tf32r(src ? src[x] : 0.f));
            }
        } else {
            for (int rs = wid; rs < 64; rs += 8) {
                int ic = rs >> 2, row = rs & 3;
                const float* src = (ic0 + ic < Cin)
                    ? inB + (long)(ic0 + ic) * plane + (long)(y0 + row) * PW : nullptr;
                float* dst = patch + ic * 264 + row * 66;
                for (int x = lane; x < 66; x += 32)
                    dst[x] = __uint_as_float(tf32r(src ? src[x] : 0.f));
            }
        }
        __syncthreads();

#pragma unroll
        for (int tap = 0; tap < 9; tap++) {
            const int dy = tap / 3, dx = tap - 3 * (tap / 3);
            const int toff = dy * rowStride + dx;
#pragma unroll
            for (int ks = 0; ks < 2; ks++) {
                const int k0 = ks * 8 + tg;
                uint32_t a[2][4];
#pragma unroll
                for (int mf = 0; mf < 2; mf++) {
                    int m = wm * 32 + mf * 16 + grp;
                    a[mf][0] = __float_as_uint(Ws[(k0 * 9 + tap) * 72 + m]);
                    a[mf][1] = __float_as_uint(Ws[(k0 * 9 + tap) * 72 + m + 8]);
                    a[mf][2] = __float_as_uint(Ws[((k0 + 4) * 9 + tap) * 72 + m]);
                    a[mf][3] = __float_as_uint(Ws[((k0 + 4) * 9 + tap) * 72 + m + 8]);
                }
#pragma unroll
                for (int nf = 0; nf < 4; nf++) {
                    uint32_t bf[2];
                    bf[0] = __float_as_uint(patch[k0 * icStride + nb[nf] + toff]);
                    bf[1] = __float_as_uint(patch[(k0 + 4) * icStride + nb[nf] + toff]);
                    MMA_TF32(acc[0][nf], a[0], bf);
                    MMA_TF32(acc[1][nf], a[1], bf);
                }
            }
        }
        __syncthreads();
    }

    float* outB = out_pad + (long)b * OC * plane;
#pragma unroll
    for (int mf = 0; mf < 2; mf++) {
        int oc = ocg * 64 + wm * 32 + mf * 16 + grp;
        float bv0 = bias[oc], bv1 = bias[oc + 8];
#pragma unroll
        for (int nf = 0; nf < 4; nf++) {
            int n = wn * 32 + nf * 8 + tg * 2;
            int py, px;
            if (R == 1) { py = ty + 1; px = x0 + 1 + n; }
            else        { py = y0 + 1 + (n >> 6); px = 1 + (n & 63); }
            float* o0 = outB + (long)oc * plane + (long)py * PW + px;
            float* o1 = outB + (long)(oc + 8) * plane + (long)py * PW + px;
            o0[0] = fmaxf(acc[mf][nf][0] + bv0, 0.f);
            o0[1] = fmaxf(acc[mf][nf][1] + bv0, 0.f);
            o1[0] = fmaxf(acc[mf][nf][2] + bv1, 0.f);
            o1[1] = fmaxf(acc[mf][nf][3] + bv1, 0.f);
        }
    }
}

// ---------------------------------------------------------------------------
// 2x2 maxpool on padded buffers
// ---------------------------------------------------------------------------
__global__ void maxpool_pad_kernel(const float* __restrict__ in, float* __restrict__ out,
                                   int C, int H, int W) {
    int Ho = H / 2, Wo = W / 2;
    long total = (long)BATCH * C * Ho * Wo;
    long i = (long)blockIdx.x * blockDim.x + threadIdx.x;
    if (i >= total) return;
    int x = (int)(i % Wo);
    long t = i / Wo;
    int y = (int)(t % Ho); t /= Ho;
    int c = (int)(t % C);
    int b = (int)(t / C);
    const float* p = in + ((long)(b * C + c) * (H + 2) + (1 + 2 * y)) * (W + 2) + 1 + 2 * x;
    float m = fmaxf(fmaxf(p[0], p[1]), fmaxf(p[W + 2], p[W + 3]));
    out[((long)(b * C + c) * (Ho + 2) + 1 + y) * (Wo + 2) + 1 + x] = m;
}

// ---------------------------------------------------------------------------
// padded features f1|f2|f3 [256][66][66] -> [B][N][C] (unnormalized)
// ---------------------------------------------------------------------------
__global__ void feat_transpose_kernel(const float* __restrict__ f1, const float* __restrict__ f2,
                                      const float* __restrict__ f3, float* __restrict__ out) {
    __shared__ float s[32][33];
    int b = blockIdx.z, c0 = blockIdx.y * 32, n0 = blockIdx.x * 32;
    const float* fb = (c0 < 256) ? f1 : (c0 < 512 ? f2 : f3);
    int cbase = c0 & 255;
    int tx = threadIdx.x, ty = threadIdx.y;   // 32 x 8
    int n = n0 + tx, y = n >> 6, x = n & 63;
    long base = (long)b * 256 * 4356;
#pragma unroll
    for (int i = 0; i < 4; i++)
        s[ty + 8 * i][tx] = fb[base + (long)(cbase + ty + 8 * i) * 4356 + (1 + y) * 66 + 1 + x];
    __syncthreads();
#pragma unroll
    for (int i = 0; i < 4; i++)
        out[((long)b * FEATN + n0 + ty + 8 * i) * FEATC + c0 + tx] = s[tx][ty + 8 * i];
}

// ---------------------------------------------------------------------------
// row L2-normalize [B*N][768] in place; one warp per row
// ---------------------------------------------------------------------------
__global__ __launch_bounds__(256)
void rownorm_rows_kernel(float* __restrict__ f) {
    int row = blockIdx.x * 8 + (threadIdx.x >> 5);
    int lane = threadIdx.x & 31;
    float* p = f + (long)row * FEATC;
    float v[24];
    float ssq = 0.f;
#pragma unroll
    for (int k = 0; k < 24; k++) {
        v[k] = p[k * 32 + lane];
        ssq = fmaf(v[k], v[k], ssq);
    }
#pragma unroll
    for (int st = 16; st > 0; st >>= 1)
        ssq += __shfl_xor_sync(0xffffffff, ssq, st);
    float inv = 1.0f / (sqrtf(ssq) + 1e-8f);
#pragma unroll
    for (int k = 0; k < 24; k++)
        p[k * 32 + lane] = v[k] * inv;
}

__global__ void initmax_kernel(float* __restrict__ g) {
    int i = blockIdx.x * blockDim.x + threadIdx.x;
    if (i < BATCH * FEATN) g[i] = 0.f;
}

// ---------------------------------------------------------------------------
// tf32 mma sim + row-max (unchanged from passing round-3 kernel)
// ---------------------------------------------------------------------------
__global__ __launch_bounds__(256)
void simmax_mma_kernel(const float* __restrict__ xT, const float* __restrict__ sT,
                       float* __restrict__ gmax) {
    __shared__ float As[128][36];
    __shared__ float Bs[128][36];

    const int b = blockIdx.z;
    const int nbase = blockIdx.y * 128;
    const int mbase = blockIdx.x * 128;
    const int tid = threadIdx.x;
    const int wid = tid >> 5, lane = tid & 31;
    const int wm = wid & 1, wn = wid >> 1;
    const int grp = lane >> 2, tg = lane & 3;

    const float* xb = xT + ((long)b * FEATN + nbase) * FEATC;
    const float* sp = sT + ((long)b * FEATN + mbase) * FEATC;

    float acc[4][4][4];
#pragma unroll
    for (int mf = 0; mf < 4; mf++)
#pragma unroll
        for (int nf = 0; nf < 4; nf++)
#pragma unroll
            for (int k = 0; k < 4; k++) acc[mf][nf][k] = 0.f;

    for (int chunk = 0; chunk < FEATC / 32; chunk++) {
        const int kc = chunk * 32;
#pragma unroll
        for (int i = 0; i < 4; i++) {
            int id = tid + i * 256;
            int r = id >> 3, q = (id & 7) * 4;
            float4 v = *(const float4*)(xb + (long)r * FEATC + kc + q);
            As[r][q + 0] = __uint_as_float(tf32r(v.x));
            As[r][q + 1] = __uint_as_float(tf32r(v.y));
            As[r][q + 2] = __uint_as_float(tf32r(v.z));
            As[r][q + 3] = __uint_as_float(tf32r(v.w));
            float4 w = *(const float4*)(sp + (long)r * FEATC + kc + q);
            Bs[r][q + 0] = __uint_as_float(tf32r(w.x));
            Bs[r][q + 1] = __uint_as_float(tf32r(w.y));
            Bs[r][q + 2] = __uint_as_float(tf32r(w.z));
            Bs[r][q + 3] = __uint_as_float(tf32r(w.w));
        }
        __syncthreads();

#pragma unroll
        for (int ks = 0; ks < 4; ks++) {
            const int kk = ks * 8;
            uint32_t a[4][4];
#pragma unroll
            for (int mf = 0; mf < 4; mf++) {
                int m0 = wm * 64 + mf * 16 + grp;
                a[mf][0] = __float_as_uint(As[m0][kk + tg]);
                a[mf][1] = __float_as_uint(As[m0 + 8][kk + tg]);
                a[mf][2] = __float_as_uint(As[m0][kk + tg + 4]);
                a[mf][3] = __float_as_uint(As[m0 + 8][kk + tg + 4]);
            }
            uint32_t bf[4][2];
#pragma unroll
            for (int nf = 0; nf < 4; nf++) {
                int n0 = wn * 32 + nf * 8 + grp;
                bf[nf][0] = __float_as_uint(Bs[n0][kk + tg]);
                bf[nf][1] = __float_as_uint(Bs[n0][kk + tg + 4]);
            }
#pragma unroll
            for (int mf = 0; mf < 4; mf++)
#pragma unroll
                for (int nf = 0; nf < 4; nf++)
                    MMA_TF32(acc[mf][nf], a[mf], bf[nf]);
        }
        __syncthreads();
    }

#pragma unroll
    for (int mf = 0; mf < 4; mf++) {
        float r0 = 0.f, r1 = 0.f;
#pragma unroll
        for (int nf = 0; nf < 4; nf++) {
            r0 = fmaxf(r0, fmaxf(acc[mf][nf][0], acc[mf][nf][1]));
            r1 = fmaxf(r1, fmaxf(acc[mf][nf][2], acc[mf][nf][3]));
        }
        r0 = fmaxf(r0, __shfl_xor_sync(0xffffffff, r0, 1));
        r0 = fmaxf(r0, __shfl_xor_sync(0xffffffff, r0, 2));
        r1 = fmaxf(r1, __shfl_xor_sync(0xffffffff, r1, 1));
        r1 = fmaxf(r1, __shfl_xor_sync(0xffffffff, r1, 2));
        if (tg == 0) {
            int row = nbase + wm * 64 + mf * 16 + grp;
            atomicMax((int*)&gmax[(long)b * FEATN + row], __float_as_int(r0));
            atomicMax((int*)&gmax[(long)b * FEATN + row + 8], __float_as_int(r1));
        }
    }
}

// ---------------------------------------------------------------------------
// final reduction
// ---------------------------------------------------------------------------
__global__ void final_loss_kernel(const float* __restrict__ gmax, float* __restrict__ out) {
    __shared__ double sm[256];
    double s = 0.0;
    for (int i = threadIdx.x; i < BATCH * FEATN; i += 256)
        s += 1.0 - (double)gmax[i];
    sm[threadIdx.x] = s;
    __syncthreads();
    for (int st = 128; st > 0; st >>= 1) {
        if (threadIdx.x < st) sm[threadIdx.x] += sm[threadIdx.x + st];
        __syncthreads();
    }
    if (threadIdx.x == 0)
        out[0] = (float)(sm[0] / (double)(BATCH * FEATN));
}

// ---------------------------------------------------------------------------
// host orchestration
// ---------------------------------------------------------------------------
#define CONV_SMEM 67584

static void run_stack(const float* img, float* wT, const float* const* bs,
                      float* pad0, float* pad1, float* pad2, float* pad3,
                      float* pad4, float* pad5, float* pad6,
                      float* f1, float* f2, float* f3, float* featT) {
    // wT segment offsets (floats)
    const long o0 = 0, o1 = 1728, o2 = 38592, o3 = 112320,
               o4 = 259776, o5 = 554688, o6 = 1144512;

    norm_input_pad_kernel<<<(BATCH * 3 * 65536 + 255) / 256, 256>>>(img, pad0);

    conv_mma_kernel<<<dim3(512, 1, BATCH), 256, CONV_SMEM>>>(pad0, wT + o0, bs[0], pad1, 3, 64, 256, 256, 1);
    conv_mma_kernel<<<dim3(512, 1, BATCH), 256, CONV_SMEM>>>(pad1, wT + o1, bs[1], pad2, 64, 64, 256, 256, 1);
    {
        long total = (long)BATCH * 64 * 128 * 128;
        maxpool_pad_kernel<<<(unsigned)((total + 255) / 256), 256>>>(pad2, pad3, 64, 256, 256);
    }
    conv_mma_kernel<<<dim3(128, 2, BATCH), 256, CONV_SMEM>>>(pad3, wT + o2, bs[2], pad4, 64, 128, 128, 128, 1);
    conv_mma_kernel<<<dim3(128, 2, BATCH), 256, CONV_SMEM>>>(pad4, wT + o3, bs[3], pad5, 128, 128, 128, 128, 1);
    {
        long total = (long)BATCH * 128 * 64 * 64;
        maxpool_pad_kernel<<<(unsigned)((total + 255) / 256), 256>>>(pad5, pad6, 128, 128, 128);
    }
    conv_mma_kernel<<<dim3(32, 4, BATCH), 256, CONV_SMEM>>>(pad6, wT + o4, bs[4], f1, 128, 256, 64, 64, 2);
    conv_mma_kernel<<<dim3(32, 4, BATCH), 256, CONV_SMEM>>>(f1, wT + o5, bs[5], f2, 256, 256, 64, 64, 2);
    conv_mma_kernel<<<dim3(32, 4, BATCH), 256, CONV_SMEM>>>(f2, wT + o6, bs[6], f3, 256, 256, 64, 64, 2);

    feat_transpose_kernel<<<dim3(128, 24, BATCH), dim3(32, 8)>>>(f1, f2, f3, featT);
    rownorm_rows_kernel<<<BATCH * FEATN / 8, 256>>>(featT);
}

extern "C" void kernel_launch(void* const* d_in, const int* in_sizes, int n_in,
                              void* d_out, int out_size) {
    (void)in_sizes; (void)n_in; (void)out_size;

    float *pad0, *pad1, *pad2, *pad3, *pad4, *pad5, *pad6, *f1, *f2, *f3;
    float *xT, *sT, *wT, *gmax;
    cudaGetSymbolAddress((void**)&pad0, g_pad0);
    cudaGetSymbolAddress((void**)&pad1, g_pad1);
    cudaGetSymbolAddress((void**)&pad2, g_pad2);
    cudaGetSymbolAddress((void**)&pad3, g_pad3);
    cudaGetSymbolAddress((void**)&pad4, g_pad4);
    cudaGetSymbolAddress((void**)&pad5, g_pad5);
    cudaGetSymbolAddress((void**)&pad6, g_pad6);
    cudaGetSymbolAddress((void**)&f1, g_f1);
    cudaGetSymbolAddress((void**)&f2, g_f2);
    cudaGetSymbolAddress((void**)&f3, g_f3);
    cudaGetSymbolAddress((void**)&xT, g_xT);
    cudaGetSymbolAddress((void**)&sT, g_sT);
    cudaGetSymbolAddress((void**)&wT, g_wT);
    cudaGetSymbolAddress((void**)&gmax, g_maxsim);

    cudaFuncSetAttribute(conv_mma_kernel, cudaFuncAttributeMaxDynamicSharedMemorySize, CONV_SMEM);

    const float* outputs = (const float*)d_in[0];
    const float* styles  = (const float*)d_in[1];
    const float* w[7];
    const float* bs[7];
    for (int i = 0; i < 7; i++) {
        w[i]  = (const float*)d_in[2 + 2 * i];
        bs[i] = (const float*)d_in[3 + 2 * i];
    }

    // zero padded buffers (borders must be 0; convs/pools only write interiors)
    zero_kernel<<<2048, 256>>>(pad0, (long)BATCH * 3 * 258 * 258);
    zero_kernel<<<2048, 256>>>(pad1, (long)BATCH * 64 * 258 * 258);
    zero_kernel<<<2048, 256>>>(pad2, (long)BATCH * 64 * 258 * 258);
    zero_kernel<<<2048, 256>>>(pad3, (long)BATCH * 64 * 130 * 130);
    zero_kernel<<<2048, 256>>>(pad4, (long)BATCH * 128 * 130 * 130);
    zero_kernel<<<2048, 256>>>(pad5, (long)BATCH * 128 * 130 * 130);
    zero_kernel<<<2048, 256>>>(pad6, (long)BATCH * 128 * 66 * 66);
    zero_kernel<<<2048, 256>>>(f1, (long)BATCH * 256 * 66 * 66);
    zero_kernel<<<2048, 256>>>(f2, (long)BATCH * 256 * 66 * 66);
    zero_kernel<<<2048, 256>>>(f3, (long)BATCH * 256 * 66 * 66);

    // weight transposes
    const int occ[7][2] = {{64,3},{64,64},{128,64},{128,128},{256,128},{256,256},{256,256}};
    const long woff[7] = {0, 1728, 38592, 112320, 259776, 554688, 1144512};
    for (int i = 0; i < 7; i++) {
        int total = occ[i][0] * occ[i][1] * 9;
        wtrans_kernel<<<(total + 255) / 256, 256>>>(w[i], wT + woff[i], occ[i][0], occ[i][1]);
    }

    run_stack(outputs, wT, bs, pad0, pad1, pad2, pad3, pad4, pad5, pad6, f1, f2, f3, xT);
    run_stack(styles,  wT, bs, pad0, pad1, pad2, pad3, pad4, pad5, pad6, f1, f2, f3, sT);

    initmax_kernel<<<(BATCH * FEATN + 255) / 256, 256>>>(gmax);
    simmax_mma_kernel<<<dim3(FEATN / 128, FEATN / 128, BATCH), 256>>>(xT, sT, gmax);
    final_loss_kernel<<<1, 256>>>(gmax, (float*)d_out);
}

// round 6
// speedup vs baseline: 3.7164x; 2.4214x over previous
#include <cuda_runtime.h>
#include <cstdint>
#include <math.h>

// ---------------------------------------------------------------------------
// VGG16-block3 features on outputs+styles [4,3,256,256], then
// loss = mean_{b,n} (1 - max_m xn[b,n].sn[b,m]),  C=768, N=M=4096.
// Activations in zero-padded [C][H+2][W+4] layout (16B-aligned rows; data at
// col 1; cols 0 and W+1..W+3 are zero pad). 3x3 conv = 9 pointer-shifted tf32
// MMA GEMMs. Weights + activations pre-rounded to tf32 at store time.
// Padded borders rely on .bss zero-init and are never written.
// ---------------------------------------------------------------------------

#define BATCH 4
#define FEATC 768
#define FEATN 4096

__device__ float g_pad0[(size_t)BATCH * 3 * 258 * 260];
__device__ float g_pad1[(size_t)BATCH * 64 * 258 * 260];
__device__ float g_pad2[(size_t)BATCH * 64 * 258 * 260];
__device__ float g_pad3[(size_t)BATCH * 64 * 130 * 132];
__device__ float g_pad4[(size_t)BATCH * 128 * 130 * 132];
__device__ float g_pad5[(size_t)BATCH * 128 * 130 * 132];
__device__ float g_pad6[(size_t)BATCH * 128 * 66 * 68];
__device__ float g_f1[(size_t)BATCH * 256 * 66 * 68];
__device__ float g_f2[(size_t)BATCH * 256 * 66 * 68];
__device__ float g_f3[(size_t)BATCH * 256 * 66 * 68];
__device__ float g_xT[(size_t)BATCH * FEATN * FEATC];
__device__ float g_sT[(size_t)BATCH * FEATN * FEATC];
__device__ float g_wT[1734336];
__device__ float g_maxsim[BATCH * FEATN];

__device__ __forceinline__ uint32_t tf32r(float x) {
    uint32_t y;
    asm("cvt.rna.tf32.f32 %0, %1;" : "=r"(y) : "f"(x));
    return y;
}
__device__ __forceinline__ float tf32f(float x) { return __uint_as_float(tf32r(x)); }

#define MMA_TF32(c, a, bfr) \
    asm volatile("mma.sync.aligned.m16n8k8.row.col.f32.tf32.tf32.f32 " \
        "{%0,%1,%2,%3}, {%4,%5,%6,%7}, {%8,%9}, {%0,%1,%2,%3};" \
        : "+f"((c)[0]), "+f"((c)[1]), "+f"((c)[2]), "+f"((c)[3]) \
        : "r"((a)[0]), "r"((a)[1]), "r"((a)[2]), "r"((a)[3]), \
          "r"((bfr)[0]), "r"((bfr)[1]))

// ---------------------------------------------------------------------------
// input normalization -> padded layout, tf32-rounded
// ---------------------------------------------------------------------------
__global__ void norm_input_pad_kernel(const float* __restrict__ in, float* __restrict__ out) {
    int i = blockIdx.x * blockDim.x + threadIdx.x;
    if (i >= BATCH * 3 * 65536) return;
    int x = i & 255, y = (i >> 8) & 255;
    int c = (i >> 16) % 3, b = i / (3 * 65536);
    const float mean[3] = {0.485f, 0.456f, 0.406f};
    const float stdv[3] = {0.229f, 0.224f, 0.225f};
    out[((size_t)(b * 3 + c) * 258 + 1 + y) * 260 + 1 + x] = tf32f((in[i] - mean[c]) / stdv[c]);
}

// ---------------------------------------------------------------------------
// weight transpose: w[oc][ic][tap] -> wT[(ic*9+tap)][oc], tf32-rounded
// ---------------------------------------------------------------------------
__global__ void wtrans_kernel(const float* __restrict__ w, float* __restrict__ wT,
                              int OC, int Cin) {
    int total = OC * Cin * 9;
    int i = blockIdx.x * blockDim.x + threadIdx.x;
    if (i >= total) return;
    int oc = i % OC, r = i / OC;
    wT[i] = tf32f(w[(size_t)oc * Cin * 9 + r]);
}

// ---------------------------------------------------------------------------
// tf32 implicit-GEMM 3x3 conv + bias + ReLU.
// Block 256 thr: 64 oc x 256 px (ROWS x COLS tile, ROWS*COLS=256).
// Warps 2(oc) x 4(px): warp tile 32 oc x 64 px. K-chunk 16 ic (144 w/ taps).
// All loads float4, no cvt (inputs pre-rounded). Output stored tf32-rounded.
// ---------------------------------------------------------------------------
template <int ROWS, int COLS>
__global__ __launch_bounds__(256, 2)
void conv_mma_kernel(const float* __restrict__ in_pad, const float* __restrict__ wT,
                     const float* __restrict__ bias, float* __restrict__ out_pad,
                     int Cin, int OC) {
    constexpr int PW = COLS + 4;
    constexpr int PR = ROWS + 2;
    constexpr int ICS = (ROWS == 2) ? (PR * PW + 8) : (PR * PW);  // mod32 in {12,24}
    extern __shared__ float smem[];
    float* Ws = smem;                  // [144][72]
    float* patch = smem + 144 * 72;    // [16][ICS]

    const int tid = threadIdx.x;
    const int wid = tid >> 5, lane = tid & 31;
    const int wm = wid & 1, wn = wid >> 1;
    const int grp = lane >> 2, tg = lane & 3;

    const int b = blockIdx.z;
    const int ocg = blockIdx.y;
    const int y0 = blockIdx.x * ROWS;
    const size_t plane = (size_t)(COLS + 2) * PW;

    const float* inB = in_pad + (size_t)b * Cin * plane;

    int nb[8];
#pragma unroll
    for (int nf = 0; nf < 8; nf++) {
        int n = wn * 64 + nf * 8 + grp;
        nb[nf] = (n / COLS) * PW + (n % COLS);
    }

    float acc[2][8][4];
#pragma unroll
    for (int mf = 0; mf < 2; mf++)
#pragma unroll
        for (int nf = 0; nf < 8; nf++)
#pragma unroll
            for (int k = 0; k < 4; k++) acc[mf][nf][k] = 0.f;

    const int m0 = wm * 32 + grp;

    for (int ic0 = 0; ic0 < Cin; ic0 += 16) {
        // weights: 144 k-rows x 64 oc, float4
        const int kvalid = min(144, (Cin - ic0) * 9);
        for (int id = tid; id < 2304; id += 256) {
            int r = id >> 4, q = (id & 15) << 2;
            float4 v = make_float4(0.f, 0.f, 0.f, 0.f);
            if (r < kvalid)
                v = *(const float4*)(wT + (size_t)(ic0 * 9 + r) * OC + ocg * 64 + q);
            *(float4*)(Ws + r * 72 + q) = v;
        }
        // patch: 16 ic x PR rows x PW floats, full rows, float4
        for (int rs = wid; rs < 16 * PR; rs += 8) {
            int ic = rs / PR, row = rs - ic * PR;
            const bool valid = (ic0 + ic) < Cin;
            const float4* src = (const float4*)(inB + (size_t)(ic0 + ic) * plane +
                                                (size_t)(y0 + row) * PW);
            float4* dst = (float4*)(patch + ic * ICS + row * PW);
#pragma unroll
            for (int x = lane; x < PW / 4; x += 32)
                dst[x] = valid ? src[x] : make_float4(0.f, 0.f, 0.f, 0.f);
        }
        __syncthreads();

#pragma unroll
        for (int tap = 0; tap < 9; tap++) {
            const int toff = (tap / 3) * PW + (tap % 3);
#pragma unroll
            for (int ks = 0; ks < 2; ks++) {
                const int k0 = ks * 8 + tg;
                uint32_t a[2][4];
#pragma unroll
                for (int mf = 0; mf < 2; mf++) {
                    int m = m0 + mf * 16;
                    a[mf][0] = __float_as_uint(Ws[(k0 * 9 + tap) * 72 + m]);
                    a[mf][1] = __float_as_uint(Ws[(k0 * 9 + tap) * 72 + m + 8]);
                    a[mf][2] = __float_as_uint(Ws[((k0 + 4) * 9 + tap) * 72 + m]);
                    a[mf][3] = __float_as_uint(Ws[((k0 + 4) * 9 + tap) * 72 + m + 8]);
                }
#pragma unroll
                for (int nf = 0; nf < 8; nf++) {
                    uint32_t bf[2];
                    bf[0] = __float_as_uint(patch[k0 * ICS + nb[nf] + toff]);
                    bf[1] = __float_as_uint(patch[(k0 + 4) * ICS + nb[nf] + toff]);
                    MMA_TF32(acc[0][nf], a[0], bf);
                    MMA_TF32(acc[1][nf], a[1], bf);
                }
            }
        }
        __syncthreads();
    }

    float* outB = out_pad + (size_t)b * OC * plane;
#pragma unroll
    for (int mf = 0; mf < 2; mf++) {
        int oc = ocg * 64 + wm * 32 + mf * 16 + grp;
        float bv0 = bias[oc], bv1 = bias[oc + 8];
#pragma unroll
        for (int nf = 0; nf < 8; nf++) {
            int n = wn * 64 + nf * 8 + tg * 2;
            int rp = n / COLS, col = n % COLS;
            float* o0 = outB + (size_t)oc * plane + (size_t)(y0 + 1 + rp) * PW + 1 + col;
            float* o1 = outB + (size_t)(oc + 8) * plane + (size_t)(y0 + 1 + rp) * PW + 1 + col;
            o0[0] = tf32f(fmaxf(acc[mf][nf][0] + bv0, 0.f));
            o0[1] = tf32f(fmaxf(acc[mf][nf][1] + bv0, 0.f));
            o1[0] = tf32f(fmaxf(acc[mf][nf][2] + bv1, 0.f));
            o1[1] = tf32f(fmaxf(acc[mf][nf][3] + bv1, 0.f));
        }
    }
}

// ---------------------------------------------------------------------------
// 2x2 maxpool on padded buffers (W+4 rows)
// ---------------------------------------------------------------------------
__global__ void maxpool_pad_kernel(const float* __restrict__ in, float* __restrict__ out,
                                   int C, int H, int W) {
    int Ho = H / 2, Wo = W / 2;
    long total = (long)BATCH * C * Ho * Wo;
    long i = (long)blockIdx.x * blockDim.x + threadIdx.x;
    if (i >= total) return;
    int x = (int)(i % Wo);
    long t = i / Wo;
    int y = (int)(t % Ho); t /= Ho;
    int c = (int)(t % C);
    int b = (int)(t / C);
    const float* p = in + ((size_t)(b * C + c) * (H + 2) + (1 + 2 * y)) * (W + 4) + 1 + 2 * x;
    float m = fmaxf(fmaxf(p[0], p[1]), fmaxf(p[W + 4], p[W + 5]));
    out[((size_t)(b * C + c) * (Ho + 2) + 1 + y) * (Wo + 4) + 1 + x] = m;
}

// ---------------------------------------------------------------------------
// padded features f1|f2|f3 [256][66][68] -> [B][N][C]
// ---------------------------------------------------------------------------
__global__ void feat_transpose_kernel(const float* __restrict__ f1, const float* __restrict__ f2,
                                      const float* __restrict__ f3, float* __restrict__ out) {
    __shared__ float s[32][33];
    int b = blockIdx.z, c0 = blockIdx.y * 32, n0 = blockIdx.x * 32;
    const float* fb = (c0 < 256) ? f1 : (c0 < 512 ? f2 : f3);
    int cbase = c0 & 255;
    int tx = threadIdx.x, ty = threadIdx.y;
    int n = n0 + tx, y = n >> 6, x = n & 63;
    size_t base = (size_t)b * 256 * 4488;
#pragma unroll
    for (int i = 0; i < 4; i++)
        s[ty + 8 * i][tx] = fb[base + (size_t)(cbase + ty + 8 * i) * 4488 + (1 + y) * 68 + 1 + x];
    __syncthreads();
#pragma unroll
    for (int i = 0; i < 4; i++)
        out[((size_t)b * FEATN + n0 + ty + 8 * i) * FEATC + c0 + tx] = s[tx][ty + 8 * i];
}

// ---------------------------------------------------------------------------
// row L2-normalize [B*N][768] in place; one warp per row
// ---------------------------------------------------------------------------
__global__ __launch_bounds__(256)
void rownorm_rows_kernel(float* __restrict__ f) {
    int row = blockIdx.x * 8 + (threadIdx.x >> 5);
    int lane = threadIdx.x & 31;
    float* p = f + (size_t)row * FEATC;
    float v[24];
    float ssq = 0.f;
#pragma unroll
    for (int k = 0; k < 24; k++) {
        v[k] = p[k * 32 + lane];
        ssq = fmaf(v[k], v[k], ssq);
    }
#pragma unroll
    for (int st = 16; st > 0; st >>= 1)
        ssq += __shfl_xor_sync(0xffffffff, ssq, st);
    float inv = 1.0f / (sqrtf(ssq) + 1e-8f);
#pragma unroll
    for (int k = 0; k < 24; k++)
        p[k * 32 + lane] = v[k] * inv;
}

__global__ void initmax_kernel(float* __restrict__ g) {
    int i = blockIdx.x * blockDim.x + threadIdx.x;
    if (i < BATCH * FEATN) g[i] = 0.f;
}

// ---------------------------------------------------------------------------
// tf32 mma sim + row-max (unchanged; proven)
// ---------------------------------------------------------------------------
__global__ __launch_bounds__(256)
void simmax_mma_kernel(const float* __restrict__ xT, const float* __restrict__ sT,
                       float* __restrict__ gmax) {
    __shared__ float As[128][36];
    __shared__ float Bs[128][36];

    const int b = blockIdx.z;
    const int nbase = blockIdx.y * 128;
    const int mbase = blockIdx.x * 128;
    const int tid = threadIdx.x;
    const int wid = tid >> 5, lane = tid & 31;
    const int wm = wid & 1, wn = wid >> 1;
    const int grp = lane >> 2, tg = lane & 3;

    const float* xb = xT + ((size_t)b * FEATN + nbase) * FEATC;
    const float* sp = sT + ((size_t)b * FEATN + mbase) * FEATC;

    float acc[4][4][4];
#pragma unroll
    for (int mf = 0; mf < 4; mf++)
#pragma unroll
        for (int nf = 0; nf < 4; nf++)
#pragma unroll
            for (int k = 0; k < 4; k++) acc[mf][nf][k] = 0.f;

    for (int chunk = 0; chunk < FEATC / 32; chunk++) {
        const int kc = chunk * 32;
#pragma unroll
        for (int i = 0; i < 4; i++) {
            int id = tid + i * 256;
            int r = id >> 3, q = (id & 7) * 4;
            float4 v = *(const float4*)(xb + (size_t)r * FEATC + kc + q);
            As[r][q + 0] = __uint_as_float(tf32r(v.x));
            As[r][q + 1] = __uint_as_float(tf32r(v.y));
            As[r][q + 2] = __uint_as_float(tf32r(v.z));
            As[r][q + 3] = __uint_as_float(tf32r(v.w));
            float4 w = *(const float4*)(sp + (size_t)r * FEATC + kc + q);
            Bs[r][q + 0] = __uint_as_float(tf32r(w.x));
            Bs[r][q + 1] = __uint_as_float(tf32r(w.y));
            Bs[r][q + 2] = __uint_as_float(tf32r(w.z));
            Bs[r][q + 3] = __uint_as_float(tf32r(w.w));
        }
        __syncthreads();

#pragma unroll
        for (int ks = 0; ks < 4; ks++) {
            const int kk = ks * 8;
            uint32_t a[4][4];
#pragma unroll
            for (int mf = 0; mf < 4; mf++) {
                int m0 = wm * 64 + mf * 16 + grp;
                a[mf][0] = __float_as_uint(As[m0][kk + tg]);
                a[mf][1] = __float_as_uint(As[m0 + 8][kk + tg]);
                a[mf][2] = __float_as_uint(As[m0][kk + tg + 4]);
                a[mf][3] = __float_as_uint(As[m0 + 8][kk + tg + 4]);
            }
            uint32_t bf[4][2];
#pragma unroll
            for (int nf = 0; nf < 4; nf++) {
                int n0 = wn * 32 + nf * 8 + grp;
                bf[nf][0] = __float_as_uint(Bs[n0][kk + tg]);
                bf[nf][1] = __float_as_uint(Bs[n0][kk + tg + 4]);
            }
#pragma unroll
            for (int mf = 0; mf < 4; mf++)
#pragma unroll
                for (int nf = 0; nf < 4; nf++)
                    MMA_TF32(acc[mf][nf], a[mf], bf[nf]);
        }
        __syncthreads();
    }

#pragma unroll
    for (int mf = 0; mf < 4; mf++) {
        float r0 = 0.f, r1 = 0.f;
#pragma unroll
        for (int nf = 0; nf < 4; nf++) {
            r0 = fmaxf(r0, fmaxf(acc[mf][nf][0], acc[mf][nf][1]));
            r1 = fmaxf(r1, fmaxf(acc[mf][nf][2], acc[mf][nf][3]));
        }
        r0 = fmaxf(r0, __shfl_xor_sync(0xffffffff, r0, 1));
        r0 = fmaxf(r0, __shfl_xor_sync(0xffffffff, r0, 2));
        r1 = fmaxf(r1, __shfl_xor_sync(0xffffffff, r1, 1));
        r1 = fmaxf(r1, __shfl_xor_sync(0xffffffff, r1, 2));
        if (tg == 0) {
            int row = nbase + wm * 64 + mf * 16 + grp;
            atomicMax((int*)&gmax[(size_t)b * FEATN + row], __float_as_int(r0));
            atomicMax((int*)&gmax[(size_t)b * FEATN + row + 8], __float_as_int(r1));
        }
    }
}

// ---------------------------------------------------------------------------
// final reduction
// ---------------------------------------------------------------------------
__global__ void final_loss_kernel(const float* __restrict__ gmax, float* __restrict__ out) {
    __shared__ double sm[256];
    double s = 0.0;
    for (int i = threadIdx.x; i < BATCH * FEATN; i += 256)
        s += 1.0 - (double)gmax[i];
    sm[threadIdx.x] = s;
    __syncthreads();
    for (int st = 128; st > 0; st >>= 1) {
        if (threadIdx.x < st) sm[threadIdx.x] += sm[threadIdx.x + st];
        __syncthreads();
    }
    if (threadIdx.x == 0)
        out[0] = (float)(sm[0] / (double)(BATCH * FEATN));
}

// ---------------------------------------------------------------------------
// host orchestration
// ---------------------------------------------------------------------------
#define SMEM_R1 ((144 * 72 + 16 * (3 * 260)) * 4)        // 91392
#define SMEM_R2 ((144 * 72 + 16 * (4 * 132 + 8)) * 4)    // 75776
#define SMEM_R4 ((144 * 72 + 16 * (6 * 68)) * 4)         // 67584

static void run_stack(const float* img, float* wT, const float* const* bs,
                      float* pad0, float* pad1, float* pad2, float* pad3,
                      float* pad4, float* pad5, float* pad6,
                      float* f1, float* f2, float* f3, float* featT) {
    const long o0 = 0, o1 = 1728, o2 = 38592, o3 = 112320,
               o4 = 259776, o5 = 554688, o6 = 1144512;

    norm_input_pad_kernel<<<(BATCH * 3 * 65536 + 255) / 256, 256>>>(img, pad0);

    conv_mma_kernel<1, 256><<<dim3(256, 1, BATCH), 256, SMEM_R1>>>(pad0, wT + o0, bs[0], pad1, 3, 64);
    conv_mma_kernel<1, 256><<<dim3(256, 1, BATCH), 256, SMEM_R1>>>(pad1, wT + o1, bs[1], pad2, 64, 64);
    {
        long total = (long)BATCH * 64 * 128 * 128;
        maxpool_pad_kernel<<<(unsigned)((total + 255) / 256), 256>>>(pad2, pad3, 64, 256, 256);
    }
    conv_mma_kernel<2, 128><<<dim3(64, 2, BATCH), 256, SMEM_R2>>>(pad3, wT + o2, bs[2], pad4, 64, 128);
    conv_mma_kernel<2, 128><<<dim3(64, 2, BATCH), 256, SMEM_R2>>>(pad4, wT + o3, bs[3], pad5, 128, 128);
    {
        long total = (long)BATCH * 128 * 64 * 64;
        maxpool_pad_kernel<<<(unsigned)((total + 255) / 256), 256>>>(pad5, pad6, 128, 128, 128);
    }
    conv_mma_kernel<4, 64><<<dim3(16, 4, BATCH), 256, SMEM_R4>>>(pad6, wT + o4, bs[4], f1, 128, 256);
    conv_mma_kernel<4, 64><<<dim3(16, 4, BATCH), 256, SMEM_R4>>>(f1, wT + o5, bs[5], f2, 256, 256);
    conv_mma_kernel<4, 64><<<dim3(16, 4, BATCH), 256, SMEM_R4>>>(f2, wT + o6, bs[6], f3, 256, 256);

    feat_transpose_kernel<<<dim3(128, 24, BATCH), dim3(32, 8)>>>(f1, f2, f3, featT);
    rownorm_rows_kernel<<<BATCH * FEATN / 8, 256>>>(featT);
}

extern "C" void kernel_launch(void* const* d_in, const int* in_sizes, int n_in,
                              void* d_out, int out_size) {
    (void)in_sizes; (void)n_in; (void)out_size;

    float *pad0, *pad1, *pad2, *pad3, *pad4, *pad5, *pad6, *f1, *f2, *f3;
    float *xT, *sT, *wT, *gmax;
    cudaGetSymbolAddress((void**)&pad0, g_pad0);
    cudaGetSymbolAddress((void**)&pad1, g_pad1);
    cudaGetSymbolAddress((void**)&pad2, g_pad2);
    cudaGetSymbolAddress((void**)&pad3, g_pad3);
    cudaGetSymbolAddress((void**)&pad4, g_pad4);
    cudaGetSymbolAddress((void**)&pad5, g_pad5);
    cudaGetSymbolAddress((void**)&pad6, g_pad6);
    cudaGetSymbolAddress((void**)&f1, g_f1);
    cudaGetSymbolAddress((void**)&f2, g_f2);
    cudaGetSymbolAddress((void**)&f3, g_f3);
    cudaGetSymbolAddress((void**)&xT, g_xT);
    cudaGetSymbolAddress((void**)&sT, g_sT);
    cudaGetSymbolAddress((void**)&wT, g_wT);
    cudaGetSymbolAddress((void**)&gmax, g_maxsim);

    cudaFuncSetAttribute(conv_mma_kernel<1, 256>, cudaFuncAttributeMaxDynamicSharedMemorySize, SMEM_R1);
    cudaFuncSetAttribute(conv_mma_kernel<2, 128>, cudaFuncAttributeMaxDynamicSharedMemorySize, SMEM_R2);
    cudaFuncSetAttribute(conv_mma_kernel<4, 64>,  cudaFuncAttributeMaxDynamicSharedMemorySize, SMEM_R4);

    const float* outputs = (const float*)d_in[0];
    const float* styles  = (const float*)d_in[1];
    const float* w[7];
    const float* bs[7];
    for (int i = 0; i < 7; i++) {
        w[i]  = (const float*)d_in[2 + 2 * i];
        bs[i] = (const float*)d_in[3 + 2 * i];
    }

    // weight transposes (tf32-rounded)
    const int occ[7][2] = {{64,3},{64,64},{128,64},{128,128},{256,128},{256,256},{256,256}};
    const long woff[7] = {0, 1728, 38592, 112320, 259776, 554688, 1144512};
    for (int i = 0; i < 7; i++) {
        int total = occ[i][0] * occ[i][1] * 9;
        wtrans_kernel<<<(total + 255) / 256, 256>>>(w[i], wT + woff[i], occ[i][0], occ[i][1]);
    }

    run_stack(outputs, wT, bs, pad0, pad1, pad2, pad3, pad4, pad5, pad6, f1, f2, f3, xT);
    run_stack(styles,  wT, bs, pad0, pad1, pad2, pad3, pad4, pad5, pad6, f1, f2, f3, sT);

    initmax_kernel<<<(BATCH * FEATN + 255) / 256, 256>>>(gmax);
    simmax_mma_kernel<<<dim3(FEATN / 128, FEATN / 128, BATCH), 256>>>(xT, sT, gmax);
    final_loss_kernel<<<1, 256>>>(gmax, (float*)d_out);
}

// round 7
// speedup vs baseline: 7.4074x; 1.9931x over previous
#include <cuda_runtime.h>
#include <cuda_fp16.h>
#include <cstdint>
#include <math.h>

// ---------------------------------------------------------------------------
// VGG16-block3 features on outputs+styles [4,3,256,256], then
// loss = mean_{b,n} (1 - max_m xn[b,n].sn[b,m]),  C=768, N=M=4096.
//
// Full fp16 datapath (fp32 accumulate) on m16n8k16 MMA.
// Activations: zero-padded channel-pair half2 layout [C/2][H+2][W+4], where
// storage pair P=(chunk c, p) holds logical channels (16c+p, 16c+8+p) — the
// (grp, grp+8) rows a fragment thread naturally owns. Weights permuted to
// match in wtrans. x and s share the layout, so the loss is unchanged.
// Padded borders rely on .bss zero-init and are never written.
// ---------------------------------------------------------------------------

#define BATCH 4
#define FEATC 768
#define FEATN 4096

__device__ __half2 g_pad0[(size_t)BATCH * 8 * 258 * 260];
__device__ __half2 g_pad1[(size_t)BATCH * 32 * 258 * 260];
__device__ __half2 g_pad2[(size_t)BATCH * 32 * 258 * 260];
__device__ __half2 g_pad3[(size_t)BATCH * 32 * 130 * 132];
__device__ __half2 g_pad4[(size_t)BATCH * 64 * 130 * 132];
__device__ __half2 g_pad5[(size_t)BATCH * 64 * 130 * 132];
__device__ __half2 g_pad6[(size_t)BATCH * 64 * 66 * 68];
__device__ __half2 g_f1[(size_t)BATCH * 128 * 66 * 68];
__device__ __half2 g_f2[(size_t)BATCH * 128 * 66 * 68];
__device__ __half2 g_f3[(size_t)BATCH * 128 * 66 * 68];
__device__ __half  g_xT[(size_t)BATCH * FEATN * FEATC];
__device__ __half  g_sT[(size_t)BATCH * FEATN * FEATC];
__device__ __half2 g_wH[870912];
__device__ float   g_maxsim[BATCH * FEATN];

#define MMA_F16(c, a, bfr) \
    asm volatile("mma.sync.aligned.m16n8k16.row.col.f32.f16.f16.f32 " \
        "{%0,%1,%2,%3}, {%4,%5,%6,%7}, {%8,%9}, {%0,%1,%2,%3};" \
        : "+f"((c)[0]), "+f"((c)[1]), "+f"((c)[2]), "+f"((c)[3]) \
        : "r"((a)[0]), "r"((a)[1]), "r"((a)[2]), "r"((a)[3]), \
          "r"((bfr)[0]), "r"((bfr)[1]))

// ---------------------------------------------------------------------------
// input normalization -> padded half2 pair layout (pairs (p, p+8); ch>=3 zero)
// ---------------------------------------------------------------------------
__global__ void norm_input_pad_kernel(const float* __restrict__ in, __half2* __restrict__ out) {
    int i = blockIdx.x * blockDim.x + threadIdx.x;
    if (i >= BATCH * 3 * 65536) return;
    int x = i & 255, y = (i >> 8) & 255;
    int c = (i >> 16) % 3, b = i / (3 * 65536);
    const float mean[3] = {0.485f, 0.456f, 0.406f};
    const float stdv[3] = {0.229f, 0.224f, 0.225f};
    float v = (in[i] - mean[c]) / stdv[c];
    out[((size_t)(b * 8 + c) * 258 + 1 + y) * 260 + 1 + x] = __floats2half2_rn(v, 0.f);
}

// ---------------------------------------------------------------------------
// weight transform: w[oc][ic][3x3] -> wH[(c*OC+oc)*72 + t*8 + p]
//   half2 = ( w[oc][16c+p][t], w[oc][16c+8+p][t] ), zeros out of range.
// ---------------------------------------------------------------------------
__global__ void wtrans_kernel(const float* __restrict__ w, __half2* __restrict__ wH,
                              int OC, int Cin, int total) {
    int i = blockIdx.x * blockDim.x + threadIdx.x;
    if (i >= total) return;
    int within = i % 72;
    int t = within >> 3, p = within & 7;
    int oc = (i / 72) % OC;
    int c = i / (72 * OC);
    int ic0 = 16 * c + p, ic1 = ic0 + 8;
    float v0 = (ic0 < Cin) ? w[((size_t)oc * Cin + ic0) * 9 + t] : 0.f;
    float v1 = (ic1 < Cin) ? w[((size_t)oc * Cin + ic1) * 9 + t] : 0.f;
    wH[i] = __floats2half2_rn(v0, v1);
}

// ---------------------------------------------------------------------------
// fp16 implicit-GEMM 3x3 conv + bias + ReLU.
// Block 256 thr: 64 oc x 256 px (ROWS x COLS, ROWS*COLS=256).
// Warps 2(oc) x 4(px): warp tile 32 oc x 64 px. K = 16 ic per MMA, per tap.
// ---------------------------------------------------------------------------
template <int ROWS, int COLS>
__global__ __launch_bounds__(256, 2)
void conv_mma_f16(const __half2* __restrict__ in, const __half2* __restrict__ wH,
                  const float* __restrict__ bias, __half2* __restrict__ out,
                  int chunks, int OC) {
    constexpr int PW2 = COLS + 4;                              // half2 per padded row
    constexpr int PR = ROWS + 2;
    constexpr int ICS2 = (PR * PW2 + 31) / 32 * 32 + 8;        // pair stride, ≡8 mod 32, mult 4
    __shared__ __align__(16) __half2 Ws2[64 * 84];             // [oc][tap*8+p], stride 84
    __shared__ __align__(16) __half2 patch2[8 * ICS2];         // [pair][row][x]

    const int tid = threadIdx.x;
    const int wid = tid >> 5, lane = tid & 31;
    const int wm = wid & 1, wn = wid >> 1;
    const int grp = lane >> 2, tg = lane & 3;

    const int b = blockIdx.z;
    const int ocg = blockIdx.y;
    const int y0 = blockIdx.x * ROWS;
    const size_t plane2 = (size_t)(COLS + 2) * PW2;

    const __half2* inB = in + (size_t)b * (chunks * 8) * plane2;
    const uint32_t* Wsu = (const uint32_t*)Ws2;
    const uint32_t* patchu = (const uint32_t*)patch2;

    int nb[8];
#pragma unroll
    for (int nf = 0; nf < 8; nf++) {
        int n = wn * 64 + nf * 8 + grp;
        nb[nf] = (n / COLS) * PW2 + (n % COLS);
    }

    float acc[2][8][4];
#pragma unroll
    for (int mf = 0; mf < 2; mf++)
#pragma unroll
        for (int nf = 0; nf < 8; nf++)
#pragma unroll
            for (int k = 0; k < 4; k++) acc[mf][nf][k] = 0.f;

    for (int c = 0; c < chunks; c++) {
        // weights: 64 oc x 72 half2, float4 copies
        const __half2* wsrc = wH + ((size_t)c * OC + ocg * 64) * 72;
        for (int id = tid; id < 1152; id += 256) {
            int oc = id / 18, q = id - oc * 18;
            ((float4*)(Ws2 + oc * 84))[q] = ((const float4*)(wsrc + oc * 72))[q];
        }
        // patch: 8 pairs x PR rows x PW2 half2, float4 copies
        for (int rs = wid; rs < 8 * PR; rs += 8) {
            int pair = rs / PR, row = rs - pair * PR;
            const float4* src = (const float4*)(inB + (size_t)(c * 8 + pair) * plane2 +
                                                (size_t)(y0 + row) * PW2);
            float4* dst = (float4*)(patch2 + pair * ICS2 + row * PW2);
#pragma unroll
            for (int x = lane; x < PW2 / 4; x += 32)
                dst[x] = src[x];
        }
        __syncthreads();

#pragma unroll
        for (int tap = 0; tap < 9; tap++) {
            const int toff = (tap / 3) * PW2 + (tap % 3);
            uint32_t a[2][4];
#pragma unroll
            for (int mf = 0; mf < 2; mf++) {
                int m = wm * 32 + mf * 16 + grp;
                a[mf][0] = Wsu[m * 84 + tap * 8 + tg];
                a[mf][1] = Wsu[(m + 8) * 84 + tap * 8 + tg];
                a[mf][2] = Wsu[m * 84 + tap * 8 + tg + 4];
                a[mf][3] = Wsu[(m + 8) * 84 + tap * 8 + tg + 4];
            }
#pragma unroll
            for (int nf = 0; nf < 8; nf++) {
                uint32_t bf[2];
                bf[0] = patchu[tg * ICS2 + nb[nf] + toff];
                bf[1] = patchu[(tg + 4) * ICS2 + nb[nf] + toff];
                MMA_F16(acc[0][nf], a[0], bf);
                MMA_F16(acc[1][nf], a[1], bf);
            }
        }
        __syncthreads();
    }

    __half2* outB = out + (size_t)b * (OC / 2) * plane2;
#pragma unroll
    for (int mf = 0; mf < 2; mf++) {
        int oc = ocg * 64 + wm * 32 + mf * 16 + grp;
        float bv0 = bias[oc], bv1 = bias[oc + 8];
        int P = (ocg * 4 + wm * 2 + mf) * 8 + grp;   // storage pair index
#pragma unroll
        for (int nf = 0; nf < 8; nf++) {
            int n = wn * 64 + nf * 8 + tg * 2;
            int rp = n / COLS, col = n % COLS;
            __half2* o = outB + (size_t)P * plane2 + (size_t)(y0 + 1 + rp) * PW2 + 1 + col;
            o[0] = __floats2half2_rn(fmaxf(acc[mf][nf][0] + bv0, 0.f),
                                     fmaxf(acc[mf][nf][2] + bv1, 0.f));
            o[1] = __floats2half2_rn(fmaxf(acc[mf][nf][1] + bv0, 0.f),
                                     fmaxf(acc[mf][nf][3] + bv1, 0.f));
        }
    }
}

// ---------------------------------------------------------------------------
// 2x2 maxpool on padded half2 buffers (channel pairing preserved)
// ---------------------------------------------------------------------------
__global__ void maxpool_pad_kernel(const __half2* __restrict__ in, __half2* __restrict__ out,
                                   int pairs, int H, int W) {
    int Ho = H / 2, Wo = W / 2;
    long total = (long)BATCH * pairs * Ho * Wo;
    long i = (long)blockIdx.x * blockDim.x + threadIdx.x;
    if (i >= total) return;
    int x = (int)(i % Wo);
    long t = i / Wo;
    int y = (int)(t % Ho); t /= Ho;
    int p = (int)(t % pairs);
    int b = (int)(t / pairs);
    const __half2* s = in + ((size_t)(b * pairs + p) * (H + 2) + (1 + 2 * y)) * (W + 4) + 1 + 2 * x;
    __half2 m = __hmax2(__hmax2(s[0], s[1]), __hmax2(s[W + 4], s[W + 5]));
    out[((size_t)(b * pairs + p) * (Ho + 2) + 1 + y) * (Wo + 4) + 1 + x] = m;
}

// ---------------------------------------------------------------------------
// padded f1|f2|f3 [128P][66][68] half2 -> [B][N][384] half2 rows
// ---------------------------------------------------------------------------
__global__ void feat_transpose_kernel(const __half2* __restrict__ f1, const __half2* __restrict__ f2,
                                      const __half2* __restrict__ f3, __half2* __restrict__ out) {
    __shared__ __half2 s[32][33];
    int b = blockIdx.z;
    int Pg = blockIdx.y * 32;                      // global pair index 0..383
    int n0 = blockIdx.x * 32;
    const __half2* fb = (Pg < 128) ? f1 : (Pg < 256 ? f2 : f3);
    int Pl = Pg & 127;
    int tx = threadIdx.x, ty = threadIdx.y;        // 32 x 8
    int n = n0 + tx, yy = n >> 6, xx = n & 63;
    size_t base = (size_t)b * 128 * 4488;
#pragma unroll
    for (int i = 0; i < 4; i++)
        s[ty + 8 * i][tx] = fb[base + (size_t)(Pl + ty + 8 * i) * 4488 + (1 + yy) * 68 + 1 + xx];
    __syncthreads();
#pragma unroll
    for (int i = 0; i < 4; i++)
        out[((size_t)b * FEATN + n0 + ty + 8 * i) * 384 + Pg + tx] = s[tx][ty + 8 * i];
}

// ---------------------------------------------------------------------------
// row L2-normalize half rows [B*N][768] in place; warp per row, fp32 math
// ---------------------------------------------------------------------------
__global__ __launch_bounds__(256)
void rownorm_rows_kernel(__half2* __restrict__ f) {
    int row = blockIdx.x * 8 + (threadIdx.x >> 5);
    int lane = threadIdx.x & 31;
    __half2* p = f + (size_t)row * 384;
    float2 v[12];
    float ssq = 0.f;
#pragma unroll
    for (int k = 0; k < 12; k++) {
        v[k] = __half22float2(p[k * 32 + lane]);
        ssq = fmaf(v[k].x, v[k].x, fmaf(v[k].y, v[k].y, ssq));
    }
#pragma unroll
    for (int st = 16; st > 0; st >>= 1)
        ssq += __shfl_xor_sync(0xffffffff, ssq, st);
    float inv = 1.0f / (sqrtf(ssq) + 1e-8f);
#pragma unroll
    for (int k = 0; k < 12; k++)
        p[k * 32 + lane] = __floats2half2_rn(v[k].x * inv, v[k].y * inv);
}

__global__ void initmax_kernel(float* __restrict__ g) {
    int i = blockIdx.x * blockDim.x + threadIdx.x;
    if (i < BATCH * FEATN) g[i] = 0.f;
}

// ---------------------------------------------------------------------------
// fp16 mma sim + row-max.  Block 128x128, warps 2x4 (64x32), K-chunk 64.
// ---------------------------------------------------------------------------
__global__ __launch_bounds__(256)
void simmax_mma_f16(const __half* __restrict__ xT, const __half* __restrict__ sT,
                    float* __restrict__ gmax) {
    __shared__ __align__(16) __half2 As2[128 * 36];
    __shared__ __align__(16) __half2 Bs2[128 * 36];

    const int b = blockIdx.z;
    const int nbase = blockIdx.y * 128;
    const int mbase = blockIdx.x * 128;
    const int tid = threadIdx.x;
    const int wid = tid >> 5, lane = tid & 31;
    const int wm = wid & 1, wn = wid >> 1;
    const int grp = lane >> 2, tg = lane & 3;

    const __half2* xb2 = (const __half2*)xT + ((size_t)b * FEATN + nbase) * 384;
    const __half2* sp2 = (const __half2*)sT + ((size_t)b * FEATN + mbase) * 384;
    const uint32_t* Au = (const uint32_t*)As2;
    const uint32_t* Bu = (const uint32_t*)Bs2;

    float acc[4][4][4];
#pragma unroll
    for (int mf = 0; mf < 4; mf++)
#pragma unroll
        for (int nf = 0; nf < 4; nf++)
#pragma unroll
            for (int k = 0; k < 4; k++) acc[mf][nf][k] = 0.f;

    for (int chunk = 0; chunk < 12; chunk++) {
        const int kc2 = chunk * 32;                 // half2 offset in row
#pragma unroll
        for (int i = 0; i < 4; i++) {
            int id = tid + i * 256;
            int r = id >> 3, q = (id & 7) * 4;
            *(float4*)(As2 + r * 36 + q) = *(const float4*)(xb2 + (size_t)r * 384 + kc2 + q);
            *(float4*)(Bs2 + r * 36 + q) = *(const float4*)(sp2 + (size_t)r * 384 + kc2 + q);
        }
        __syncthreads();

#pragma unroll
        for (int ks = 0; ks < 4; ks++) {
            const int kk = ks * 8;
            uint32_t a[4][4];
#pragma unroll
            for (int mf = 0; mf < 4; mf++) {
                int m = wm * 64 + mf * 16 + grp;
                a[mf][0] = Au[m * 36 + kk + tg];
                a[mf][1] = Au[(m + 8) * 36 + kk + tg];
                a[mf][2] = Au[m * 36 + kk + tg + 4];
                a[mf][3] = Au[(m + 8) * 36 + kk + tg + 4];
            }
#pragma unroll
            for (int nf = 0; nf < 4; nf++) {
                int n = wn * 32 + nf * 8 + grp;
                uint32_t bf[2];
                bf[0] = Bu[n * 36 + kk + tg];
                bf[1] = Bu[n * 36 + kk + tg + 4];
                MMA_F16(acc[0][nf], a[0], bf);
                MMA_F16(acc[1][nf], a[1], bf);
                MMA_F16(acc[2][nf], a[2], bf);
                MMA_F16(acc[3][nf], a[3], bf);
            }
        }
        __syncthreads();
    }

#pragma unroll
    for (int mf = 0; mf < 4; mf++) {
        float r0 = 0.f, r1 = 0.f;
#pragma unroll
        for (int nf = 0; nf < 4; nf++) {
            r0 = fmaxf(r0, fmaxf(acc[mf][nf][0], acc[mf][nf][1]));
            r1 = fmaxf(r1, fmaxf(acc[mf][nf][2], acc[mf][nf][3]));
        }
        r0 = fmaxf(r0, __shfl_xor_sync(0xffffffff, r0, 1));
        r0 = fmaxf(r0, __shfl_xor_sync(0xffffffff, r0, 2));
        r1 = fmaxf(r1, __shfl_xor_sync(0xffffffff, r1, 1));
        r1 = fmaxf(r1, __shfl_xor_sync(0xffffffff, r1, 2));
        if (tg == 0) {
            int row = nbase + wm * 64 + mf * 16 + grp;
            atomicMax((int*)&gmax[(size_t)b * FEATN + row], __float_as_int(r0));
            atomicMax((int*)&gmax[(size_t)b * FEATN + row + 8], __float_as_int(r1));
        }
    }
}

// ---------------------------------------------------------------------------
// final reduction
// ---------------------------------------------------------------------------
__global__ void final_loss_kernel(const float* __restrict__ gmax, float* __restrict__ out) {
    __shared__ double sm[256];
    double s = 0.0;
    for (int i = threadIdx.x; i < BATCH * FEATN; i += 256)
        s += 1.0 - (double)gmax[i];
    sm[threadIdx.x] = s;
    __syncthreads();
    for (int st = 128; st > 0; st >>= 1) {
        if (threadIdx.x < st) sm[threadIdx.x] += sm[threadIdx.x + st];
        __syncthreads();
    }
    if (threadIdx.x == 0)
        out[0] = (float)(sm[0] / (double)(BATCH * FEATN));
}

// ---------------------------------------------------------------------------
// host orchestration
// ---------------------------------------------------------------------------
static void run_stack(const float* img, __half2* wH, const float* const* bs,
                      __half2* pad0, __half2* pad1, __half2* pad2, __half2* pad3,
                      __half2* pad4, __half2* pad5, __half2* pad6,
                      __half2* f1, __half2* f2, __half2* f3, __half* featT) {
    // wH segment offsets (half2 units)
    const long o0 = 0, o1 = 4608, o2 = 23040, o3 = 59904,
               o4 = 133632, o5 = 281088, o6 = 576000;

    norm_input_pad_kernel<<<(BATCH * 3 * 65536 + 255) / 256, 256>>>(img, pad0);

    conv_mma_f16<1, 256><<<dim3(256, 1, BATCH), 256>>>(pad0, wH + o0, bs[0], pad1, 1, 64);
    conv_mma_f16<1, 256><<<dim3(256, 1, BATCH), 256>>>(pad1, wH + o1, bs[1], pad2, 4, 64);
    {
        long total = (long)BATCH * 32 * 128 * 128;
        maxpool_pad_kernel<<<(unsigned)((total + 255) / 256), 256>>>(pad2, pad3, 32, 256, 256);
    }
    conv_mma_f16<2, 128><<<dim3(64, 2, BATCH), 256>>>(pad3, wH + o2, bs[2], pad4, 4, 128);
    conv_mma_f16<2, 128><<<dim3(64, 2, BATCH), 256>>>(pad4, wH + o3, bs[3], pad5, 8, 128);
    {
        long total = (long)BATCH * 64 * 64 * 64;
        maxpool_pad_kernel<<<(unsigned)((total + 255) / 256), 256>>>(pad5, pad6, 64, 128, 128);
    }
    conv_mma_f16<4, 64><<<dim3(16, 4, BATCH), 256>>>(pad6, wH + o4, bs[4], f1, 8, 256);
    conv_mma_f16<4, 64><<<dim3(16, 4, BATCH), 256>>>(f1, wH + o5, bs[5], f2, 16, 256);
    conv_mma_f16<4, 64><<<dim3(16, 4, BATCH), 256>>>(f2, wH + o6, bs[6], f3, 16, 256);

    feat_transpose_kernel<<<dim3(128, 12, BATCH), dim3(32, 8)>>>(f1, f2, f3, (__half2*)featT);
    rownorm_rows_kernel<<<BATCH * FEATN / 8, 256>>>((__half2*)featT);
}

extern "C" void kernel_launch(void* const* d_in, const int* in_sizes, int n_in,
                              void* d_out, int out_size) {
    (void)in_sizes; (void)n_in; (void)out_size;

    __half2 *pad0, *pad1, *pad2, *pad3, *pad4, *pad5, *pad6, *f1, *f2, *f3, *wH;
    __half *xT, *sT;
    float *gmax;
    cudaGetSymbolAddress((void**)&pad0, g_pad0);
    cudaGetSymbolAddress((void**)&pad1, g_pad1);
    cudaGetSymbolAddress((void**)&pad2, g_pad2);
    cudaGetSymbolAddress((void**)&pad3, g_pad3);
    cudaGetSymbolAddress((void**)&pad4, g_pad4);
    cudaGetSymbolAddress((void**)&pad5, g_pad5);
    cudaGetSymbolAddress((void**)&pad6, g_pad6);
    cudaGetSymbolAddress((void**)&f1, g_f1);
    cudaGetSymbolAddress((void**)&f2, g_f2);
    cudaGetSymbolAddress((void**)&f3, g_f3);
    cudaGetSymbolAddress((void**)&xT, g_xT);
    cudaGetSymbolAddress((void**)&sT, g_sT);
    cudaGetSymbolAddress((void**)&wH, g_wH);
    cudaGetSymbolAddress((void**)&gmax, g_maxsim);

    const float* outputs = (const float*)d_in[0];
    const float* styles  = (const float*)d_in[1];
    const float* w[7];
    const float* bs[7];
    for (int i = 0; i < 7; i++) {
        w[i]  = (const float*)d_in[2 + 2 * i];
        bs[i] = (const float*)d_in[3 + 2 * i];
    }

    // weight transforms (pair-permuted, fp16)
    const int cfg[7][3] = {{64,3,1},{64,64,4},{128,64,4},{128,128,8},
                           {256,128,8},{256,256,16},{256,256,16}};
    const long woff[7] = {0, 4608, 23040, 59904, 133632, 281088, 576000};
    for (int i = 0; i < 7; i++) {
        int total = cfg[i][2] * cfg[i][0] * 72;
        wtrans_kernel<<<(total + 255) / 256, 256>>>(w[i], wH + woff[i], cfg[i][0], cfg[i][1], total);
    }

    run_stack(outputs, wH, bs, pad0, pad1, pad2, pad3, pad4, pad5, pad6, f1, f2, f3, xT);
    run_stack(styles,  wH, bs, pad0, pad1, pad2, pad3, pad4, pad5, pad6, f1, f2, f3, sT);

    initmax_kernel<<<(BATCH * FEATN + 255) / 256, 256>>>(gmax);
    simmax_mma_f16<<<dim3(FEATN / 128, FEATN / 128, BATCH), 256>>>(xT, sT, gmax);
    final_loss_kernel<<<1, 256>>>(gmax, (float*)d_out);
}

// round 8
// speedup vs baseline: 9.8409x; 1.3285x over previous
#include <cuda_runtime.h>
#include <cuda_fp16.h>
#include <cstdint>
#include <math.h>

// ---------------------------------------------------------------------------
// VGG16-block3 features on outputs+styles [4,3,256,256], then
// loss = mean_{b,n} (1 - max_m xn[b,n].sn[b,m]),  C=768, N=M=4096.
//
// Full fp16 datapath (fp32 accumulate) on m16n8k16 MMA, cp.async-pipelined.
// Activations: zero-padded channel-pair half2 layout [C/2][H+2][W+4]; storage
// pair P=(chunk c, p) holds logical channels (16c+p, 16c+8+p). Weights
// permuted to match. Padded borders rely on .bss zero-init, never written.
// ---------------------------------------------------------------------------

#define BATCH 4
#define FEATC 768
#define FEATN 4096

__device__ __half2 g_pad0[(size_t)BATCH * 8 * 258 * 260];
__device__ __half2 g_pad1[(size_t)BATCH * 32 * 258 * 260];
__device__ __half2 g_pad2[(size_t)BATCH * 32 * 258 * 260];
__device__ __half2 g_pad3[(size_t)BATCH * 32 * 130 * 132];
__device__ __half2 g_pad4[(size_t)BATCH * 64 * 130 * 132];
__device__ __half2 g_pad5[(size_t)BATCH * 64 * 130 * 132];
__device__ __half2 g_pad6[(size_t)BATCH * 64 * 66 * 68];
__device__ __half2 g_f1[(size_t)BATCH * 128 * 66 * 68];
__device__ __half2 g_f2[(size_t)BATCH * 128 * 66 * 68];
__device__ __half2 g_f3[(size_t)BATCH * 128 * 66 * 68];
__device__ __half  g_xT[(size_t)BATCH * FEATN * FEATC];
__device__ __half  g_sT[(size_t)BATCH * FEATN * FEATC];
__device__ __half2 g_wH[870912];
__device__ float   g_maxsim[BATCH * FEATN];

#define MMA_F16(c, a, bfr) \
    asm volatile("mma.sync.aligned.m16n8k16.row.col.f32.f16.f16.f32 " \
        "{%0,%1,%2,%3}, {%4,%5,%6,%7}, {%8,%9}, {%0,%1,%2,%3};" \
        : "+f"((c)[0]), "+f"((c)[1]), "+f"((c)[2]), "+f"((c)[3]) \
        : "r"((a)[0]), "r"((a)[1]), "r"((a)[2]), "r"((a)[3]), \
          "r"((bfr)[0]), "r"((bfr)[1]))

__device__ __forceinline__ void cpa16(uint32_t dst, const void* src) {
    asm volatile("cp.async.cg.shared.global [%0], [%1], 16;" :: "r"(dst), "l"(src));
}
#define CPA_COMMIT() asm volatile("cp.async.commit_group;" ::: "memory")
#define CPA_WAIT1()  asm volatile("cp.async.wait_group 1;" ::: "memory")
#define CPA_WAIT0()  asm volatile("cp.async.wait_group 0;" ::: "memory")

// ---------------------------------------------------------------------------
// input normalization -> padded half2 pair layout (pairs (p, p+8); ch>=3 zero)
// ---------------------------------------------------------------------------
__global__ void norm_input_pad_kernel(const float* __restrict__ in, __half2* __restrict__ out) {
    int i = blockIdx.x * blockDim.x + threadIdx.x;
    if (i >= BATCH * 3 * 65536) return;
    int x = i & 255, y = (i >> 8) & 255;
    int c = (i >> 16) % 3, b = i / (3 * 65536);
    const float mean[3] = {0.485f, 0.456f, 0.406f};
    const float stdv[3] = {0.229f, 0.224f, 0.225f};
    float v = (in[i] - mean[c]) / stdv[c];
    out[((size_t)(b * 8 + c) * 258 + 1 + y) * 260 + 1 + x] = __floats2half2_rn(v, 0.f);
}

// ---------------------------------------------------------------------------
// weight transform: w[oc][ic][3x3] -> wH[(c*OC+oc)*72 + t*8 + p]
// ---------------------------------------------------------------------------
__global__ void wtrans_kernel(const float* __restrict__ w, __half2* __restrict__ wH,
                              int OC, int Cin, int total) {
    int i = blockIdx.x * blockDim.x + threadIdx.x;
    if (i >= total) return;
    int within = i % 72;
    int t = within >> 3, p = within & 7;
    int oc = (i / 72) % OC;
    int c = i / (72 * OC);
    int ic0 = 16 * c + p, ic1 = ic0 + 8;
    float v0 = (ic0 < Cin) ? w[((size_t)oc * Cin + ic0) * 9 + t] : 0.f;
    float v1 = (ic1 < Cin) ? w[((size_t)oc * Cin + ic1) * 9 + t] : 0.f;
    wH[i] = __floats2half2_rn(v0, v1);
}

// ---------------------------------------------------------------------------
// fp16 implicit-GEMM 3x3 conv + bias + ReLU, cp.async double-buffered.
// Block 256 thr: 64 oc x 256 px (ROWS x COLS). Warps 2(oc) x 4(px).
// ---------------------------------------------------------------------------
template <int ROWS, int COLS>
__global__ __launch_bounds__(256, 2)
void conv_mma_f16(const __half2* __restrict__ in, const __half2* __restrict__ wH,
                  const float* __restrict__ bias, __half2* __restrict__ out,
                  int chunks, int OC) {
    constexpr int PW2 = COLS + 4;
    constexpr int PR = ROWS + 2;
    constexpr int ICS2 = (PR * PW2 + 31) / 32 * 32 + 8;     // ≡8 mod 32, mult of 4
    constexpr int WS_SIZE = 64 * 84;                        // half2 units
    constexpr int PATCH_SIZE = 8 * ICS2;
    constexpr int BUF = WS_SIZE + PATCH_SIZE;
    extern __shared__ __half2 sm[];

    const int tid = threadIdx.x;
    const int wid = tid >> 5, lane = tid & 31;
    const int wm = wid & 1, wn = wid >> 1;
    const int grp = lane >> 2, tg = lane & 3;

    const int b = blockIdx.z;
    const int ocg = blockIdx.y;
    const int y0 = blockIdx.x * ROWS;
    const size_t plane2 = (size_t)(COLS + 2) * PW2;

    const __half2* inB = in + (size_t)b * (chunks * 8) * plane2;
    const uint32_t sm_u32 = (uint32_t)__cvta_generic_to_shared(sm);

    int nb[8];
#pragma unroll
    for (int nf = 0; nf < 8; nf++) {
        int n = wn * 64 + nf * 8 + grp;
        nb[nf] = (n / COLS) * PW2 + (n % COLS);
    }

    float acc[2][8][4];
#pragma unroll
    for (int mf = 0; mf < 2; mf++)
#pragma unroll
        for (int nf = 0; nf < 8; nf++)
#pragma unroll
            for (int k = 0; k < 4; k++) acc[mf][nf][k] = 0.f;

    auto prefetch = [&](int c, int bi) {
        const __half2* wsrc = wH + ((size_t)c * OC + ocg * 64) * 72;
        uint32_t wdst = sm_u32 + (uint32_t)(bi * BUF) * 4;
        for (int id = tid; id < 1152; id += 256) {
            int oc = id / 18, q = id - oc * 18;
            cpa16(wdst + (oc * 84 + q * 4) * 4, wsrc + oc * 72 + q * 4);
        }
        uint32_t pdst = sm_u32 + (uint32_t)(bi * BUF + WS_SIZE) * 4;
        for (int rs = wid; rs < 8 * PR; rs += 8) {
            int pair = rs / PR, row = rs - pair * PR;
            const __half2* src = inB + (size_t)(c * 8 + pair) * plane2 + (size_t)(y0 + row) * PW2;
            uint32_t dst = pdst + (pair * ICS2 + row * PW2) * 4;
            for (int x = lane; x < PW2 / 4; x += 32)
                cpa16(dst + x * 16, src + x * 4);
        }
    };

    prefetch(0, 0);
    CPA_COMMIT();

    for (int c = 0; c < chunks; c++) {
        const int bi = c & 1;
        if (c > 0) __syncthreads();           // compute(c-1) done before overwriting its buffer
        if (c + 1 < chunks) {
            prefetch(c + 1, bi ^ 1);
            CPA_COMMIT();
            CPA_WAIT1();
        } else {
            CPA_WAIT0();
        }
        __syncthreads();

        const uint32_t* Wsu = (const uint32_t*)(sm + bi * BUF);
        const uint32_t* patchu = (const uint32_t*)(sm + bi * BUF + WS_SIZE);

#pragma unroll
        for (int tap = 0; tap < 9; tap++) {
            const int toff = (tap / 3) * PW2 + (tap % 3);
            uint32_t a[2][4];
#pragma unroll
            for (int mf = 0; mf < 2; mf++) {
                int m = wm * 32 + mf * 16 + grp;
                a[mf][0] = Wsu[m * 84 + tap * 8 + tg];
                a[mf][1] = Wsu[(m + 8) * 84 + tap * 8 + tg];
                a[mf][2] = Wsu[m * 84 + tap * 8 + tg + 4];
                a[mf][3] = Wsu[(m + 8) * 84 + tap * 8 + tg + 4];
            }
#pragma unroll
            for (int nf = 0; nf < 8; nf++) {
                uint32_t bf[2];
                bf[0] = patchu[tg * ICS2 + nb[nf] + toff];
                bf[1] = patchu[(tg + 4) * ICS2 + nb[nf] + toff];
                MMA_F16(acc[0][nf], a[0], bf);
                MMA_F16(acc[1][nf], a[1], bf);
            }
        }
    }

    __half2* outB = out + (size_t)b * (OC / 2) * plane2;
#pragma unroll
    for (int mf = 0; mf < 2; mf++) {
        int oc = ocg * 64 + wm * 32 + mf * 16 + grp;
        float bv0 = bias[oc], bv1 = bias[oc + 8];
        int P = (ocg * 4 + wm * 2 + mf) * 8 + grp;
#pragma unroll
        for (int nf = 0; nf < 8; nf++) {
            int n = wn * 64 + nf * 8 + tg * 2;
            int rp = n / COLS, col = n % COLS;
            __half2* o = outB + (size_t)P * plane2 + (size_t)(y0 + 1 + rp) * PW2 + 1 + col;
            o[0] = __floats2half2_rn(fmaxf(acc[mf][nf][0] + bv0, 0.f),
                                     fmaxf(acc[mf][nf][2] + bv1, 0.f));
            o[1] = __floats2half2_rn(fmaxf(acc[mf][nf][1] + bv0, 0.f),
                                     fmaxf(acc[mf][nf][3] + bv1, 0.f));
        }
    }
}

// ---------------------------------------------------------------------------
// 2x2 maxpool on padded half2 buffers
// ---------------------------------------------------------------------------
__global__ void maxpool_pad_kernel(const __half2* __restrict__ in, __half2* __restrict__ out,
                                   int pairs, int H, int W) {
    int Ho = H / 2, Wo = W / 2;
    long total = (long)BATCH * pairs * Ho * Wo;
    long i = (long)blockIdx.x * blockDim.x + threadIdx.x;
    if (i >= total) return;
    int x = (int)(i % Wo);
    long t = i / Wo;
    int y = (int)(t % Ho); t /= Ho;
    int p = (int)(t % pairs);
    int b = (int)(t / pairs);
    const __half2* s = in + ((size_t)(b * pairs + p) * (H + 2) + (1 + 2 * y)) * (W + 4) + 1 + 2 * x;
    __half2 m = __hmax2(__hmax2(s[0], s[1]), __hmax2(s[W + 4], s[W + 5]));
    out[((size_t)(b * pairs + p) * (Ho + 2) + 1 + y) * (Wo + 4) + 1 + x] = m;
}

// ---------------------------------------------------------------------------
// padded f1|f2|f3 [128P][66][68] half2 -> [B][N][384] half2 rows
// ---------------------------------------------------------------------------
__global__ void feat_transpose_kernel(const __half2* __restrict__ f1, const __half2* __restrict__ f2,
                                      const __half2* __restrict__ f3, __half2* __restrict__ out) {
    __shared__ __half2 s[32][33];
    int b = blockIdx.z;
    int Pg = blockIdx.y * 32;
    int n0 = blockIdx.x * 32;
    const __half2* fb = (Pg < 128) ? f1 : (Pg < 256 ? f2 : f3);
    int Pl = Pg & 127;
    int tx = threadIdx.x, ty = threadIdx.y;
    int n = n0 + tx, yy = n >> 6, xx = n & 63;
    size_t base = (size_t)b * 128 * 4488;
#pragma unroll
    for (int i = 0; i < 4; i++)
        s[ty + 8 * i][tx] = fb[base + (size_t)(Pl + ty + 8 * i) * 4488 + (1 + yy) * 68 + 1 + xx];
    __syncthreads();
#pragma unroll
    for (int i = 0; i < 4; i++)
        out[((size_t)b * FEATN + n0 + ty + 8 * i) * 384 + Pg + tx] = s[tx][ty + 8 * i];
}

// ---------------------------------------------------------------------------
// row L2-normalize half rows [B*N][768] in place; warp per row, fp32 math
// ---------------------------------------------------------------------------
__global__ __launch_bounds__(256)
void rownorm_rows_kernel(__half2* __restrict__ f) {
    int row = blockIdx.x * 8 + (threadIdx.x >> 5);
    int lane = threadIdx.x & 31;
    __half2* p = f + (size_t)row * 384;
    float2 v[12];
    float ssq = 0.f;
#pragma unroll
    for (int k = 0; k < 12; k++) {
        v[k] = __half22float2(p[k * 32 + lane]);
        ssq = fmaf(v[k].x, v[k].x, fmaf(v[k].y, v[k].y, ssq));
    }
#pragma unroll
    for (int st = 16; st > 0; st >>= 1)
        ssq += __shfl_xor_sync(0xffffffff, ssq, st);
    float inv = 1.0f / (sqrtf(ssq) + 1e-8f);
#pragma unroll
    for (int k = 0; k < 12; k++)
        p[k * 32 + lane] = __floats2half2_rn(v[k].x * inv, v[k].y * inv);
}

__global__ void initmax_kernel(float* __restrict__ g) {
    int i = blockIdx.x * blockDim.x + threadIdx.x;
    if (i < BATCH * FEATN) g[i] = 0.f;
}

// ---------------------------------------------------------------------------
// fp16 mma sim + row-max, cp.async double-buffered.
// Block 128x128, warps 2x4 (64x32), K-chunk 64 (32 half2), 12 chunks.
// ---------------------------------------------------------------------------
#define SIM_TILE 4608   // 128*36 half2 per As/Bs

__global__ __launch_bounds__(256, 2)
void simmax_mma_f16(const __half* __restrict__ xT, const __half* __restrict__ sT,
                    float* __restrict__ gmax) {
    extern __shared__ __half2 sm[];   // [As0][Bs0][As1][Bs1]

    const int b = blockIdx.z;
    const int nbase = blockIdx.y * 128;
    const int mbase = blockIdx.x * 128;
    const int tid = threadIdx.x;
    const int wid = tid >> 5, lane = tid & 31;
    const int wm = wid & 1, wn = wid >> 1;
    const int grp = lane >> 2, tg = lane & 3;

    const __half2* xb2 = (const __half2*)xT + ((size_t)b * FEATN + nbase) * 384;
    const __half2* sp2 = (const __half2*)sT + ((size_t)b * FEATN + mbase) * 384;
    const uint32_t sm_u32 = (uint32_t)__cvta_generic_to_shared(sm);

    float acc[4][4][4];
#pragma unroll
    for (int mf = 0; mf < 4; mf++)
#pragma unroll
        for (int nf = 0; nf < 4; nf++)
#pragma unroll
            for (int k = 0; k < 4; k++) acc[mf][nf][k] = 0.f;

    auto prefetch = [&](int chunk, int bi) {
        const int kc2 = chunk * 32;
        uint32_t abase = sm_u32 + (uint32_t)(bi * 2 * SIM_TILE) * 4;
        uint32_t bbase = abase + SIM_TILE * 4;
#pragma unroll
        for (int i = 0; i < 4; i++) {
            int id = tid + i * 256;
            int r = id >> 3, q = (id & 7) * 4;
            cpa16(abase + (r * 36 + q) * 4, xb2 + (size_t)r * 384 + kc2 + q);
            cpa16(bbase + (r * 36 + q) * 4, sp2 + (size_t)r * 384 + kc2 + q);
        }
    };

    prefetch(0, 0);
    CPA_COMMIT();

    for (int chunk = 0; chunk < 12; chunk++) {
        const int bi = chunk & 1;
        if (chunk > 0) __syncthreads();
        if (chunk + 1 < 12) {
            prefetch(chunk + 1, bi ^ 1);
            CPA_COMMIT();
            CPA_WAIT1();
        } else {
            CPA_WAIT0();
        }
        __syncthreads();

        const uint32_t* Au = (const uint32_t*)(sm + bi * 2 * SIM_TILE);
        const uint32_t* Bu = Au + SIM_TILE;

#pragma unroll
        for (int ks = 0; ks < 4; ks++) {
            const int kk = ks * 8;
            uint32_t a[4][4];
#pragma unroll
            for (int mf = 0; mf < 4; mf++) {
                int m = wm * 64 + mf * 16 + grp;
                a[mf][0] = Au[m * 36 + kk + tg];
                a[mf][1] = Au[(m + 8) * 36 + kk + tg];
                a[mf][2] = Au[m * 36 + kk + tg + 4];
                a[mf][3] = Au[(m + 8) * 36 + kk + tg + 4];
            }
#pragma unroll
            for (int nf = 0; nf < 4; nf++) {
                int n = wn * 32 + nf * 8 + grp;
                uint32_t bf[2];
                bf[0] = Bu[n * 36 + kk + tg];
                bf[1] = Bu[n * 36 + kk + tg + 4];
                MMA_F16(acc[0][nf], a[0], bf);
                MMA_F16(acc[1][nf], a[1], bf);
                MMA_F16(acc[2][nf], a[2], bf);
                MMA_F16(acc[3][nf], a[3], bf);
            }
        }
    }

#pragma unroll
    for (int mf = 0; mf < 4; mf++) {
        float r0 = 0.f, r1 = 0.f;
#pragma unroll
        for (int nf = 0; nf < 4; nf++) {
            r0 = fmaxf(r0, fmaxf(acc[mf][nf][0], acc[mf][nf][1]));
            r1 = fmaxf(r1, fmaxf(acc[mf][nf][2], acc[mf][nf][3]));
        }
        r0 = fmaxf(r0, __shfl_xor_sync(0xffffffff, r0, 1));
        r0 = fmaxf(r0, __shfl_xor_sync(0xffffffff, r0, 2));
        r1 = fmaxf(r1, __shfl_xor_sync(0xffffffff, r1, 1));
        r1 = fmaxf(r1, __shfl_xor_sync(0xffffffff, r1, 2));
        if (tg == 0) {
            int row = nbase + wm * 64 + mf * 16 + grp;
            atomicMax((int*)&gmax[(size_t)b * FEATN + row], __float_as_int(r0));
            atomicMax((int*)&gmax[(size_t)b * FEATN + row + 8], __float_as_int(r1));
        }
    }
}

// ---------------------------------------------------------------------------
// final reduction
// ---------------------------------------------------------------------------
__global__ void final_loss_kernel(const float* __restrict__ gmax, float* __restrict__ out) {
    __shared__ double sm[256];
    double s = 0.0;
    for (int i = threadIdx.x; i < BATCH * FEATN; i += 256)
        s += 1.0 - (double)gmax[i];
    sm[threadIdx.x] = s;
    __syncthreads();
    for (int st = 128; st > 0; st >>= 1) {
        if (threadIdx.x < st) sm[threadIdx.x] += sm[threadIdx.x + st];
        __syncthreads();
    }
    if (threadIdx.x == 0)
        out[0] = (float)(sm[0] / (double)(BATCH * FEATN));
}

// ---------------------------------------------------------------------------
// host orchestration
// ---------------------------------------------------------------------------
static constexpr int conv_smem(int R, int C) {
    int PW2 = C + 4, PR = R + 2;
    int ICS2 = (PR * PW2 + 31) / 32 * 32 + 8;
    return 2 * (64 * 84 + 8 * ICS2) * 4;
}
#define CS_R1 conv_smem(1, 256)
#define CS_R2 conv_smem(2, 128)
#define CS_R4 conv_smem(4, 64)
#define SIM_SMEM (4 * SIM_TILE * 4)

static void run_stack(const float* img, __half2* wH, const float* const* bs,
                      __half2* pad0, __half2* pad1, __half2* pad2, __half2* pad3,
                      __half2* pad4, __half2* pad5, __half2* pad6,
                      __half2* f1, __half2* f2, __half2* f3, __half* featT) {
    const long o0 = 0, o1 = 4608, o2 = 23040, o3 = 59904,
               o4 = 133632, o5 = 281088, o6 = 576000;

    norm_input_pad_kernel<<<(BATCH * 3 * 65536 + 255) / 256, 256>>>(img, pad0);

    conv_mma_f16<1, 256><<<dim3(256, 1, BATCH), 256, CS_R1>>>(pad0, wH + o0, bs[0], pad1, 1, 64);
    conv_mma_f16<1, 256><<<dim3(256, 1, BATCH), 256, CS_R1>>>(pad1, wH + o1, bs[1], pad2, 4, 64);
    {
        long total = (long)BATCH * 32 * 128 * 128;
        maxpool_pad_kernel<<<(unsigned)((total + 255) / 256), 256>>>(pad2, pad3, 32, 256, 256);
    }
    conv_mma_f16<2, 128><<<dim3(64, 2, BATCH), 256, CS_R2>>>(pad3, wH + o2, bs[2], pad4, 4, 128);
    conv_mma_f16<2, 128><<<dim3(64, 2, BATCH), 256, CS_R2>>>(pad4, wH + o3, bs[3], pad5, 8, 128);
    {
        long total = (long)BATCH * 64 * 64 * 64;
        maxpool_pad_kernel<<<(unsigned)((total + 255) / 256), 256>>>(pad5, pad6, 64, 128, 128);
    }
    conv_mma_f16<4, 64><<<dim3(16, 4, BATCH), 256, CS_R4>>>(pad6, wH + o4, bs[4], f1, 8, 256);
    conv_mma_f16<4, 64><<<dim3(16, 4, BATCH), 256, CS_R4>>>(f1, wH + o5, bs[5], f2, 16, 256);
    conv_mma_f16<4, 64><<<dim3(16, 4, BATCH), 256, CS_R4>>>(f2, wH + o6, bs[6], f3, 16, 256);

    feat_transpose_kernel<<<dim3(128, 12, BATCH), dim3(32, 8)>>>(f1, f2, f3, (__half2*)featT);
    rownorm_rows_kernel<<<BATCH * FEATN / 8, 256>>>((__half2*)featT);
}

extern "C" void kernel_launch(void* const* d_in, const int* in_sizes, int n_in,
                              void* d_out, int out_size) {
    (void)in_sizes; (void)n_in; (void)out_size;

    __half2 *pad0, *pad1, *pad2, *pad3, *pad4, *pad5, *pad6, *f1, *f2, *f3, *wH;
    __half *xT, *sT;
    float *gmax;
    cudaGetSymbolAddress((void**)&pad0, g_pad0);
    cudaGetSymbolAddress((void**)&pad1, g_pad1);
    cudaGetSymbolAddress((void**)&pad2, g_pad2);
    cudaGetSymbolAddress((void**)&pad3, g_pad3);
    cudaGetSymbolAddress((void**)&pad4, g_pad4);
    cudaGetSymbolAddress((void**)&pad5, g_pad5);
    cudaGetSymbolAddress((void**)&pad6, g_pad6);
    cudaGetSymbolAddress((void**)&f1, g_f1);
    cudaGetSymbolAddress((void**)&f2, g_f2);
    cudaGetSymbolAddress((void**)&f3, g_f3);
    cudaGetSymbolAddress((void**)&xT, g_xT);
    cudaGetSymbolAddress((void**)&sT, g_sT);
    cudaGetSymbolAddress((void**)&wH, g_wH);
    cudaGetSymbolAddress((void**)&gmax, g_maxsim);

    cudaFuncSetAttribute(conv_mma_f16<1, 256>, cudaFuncAttributeMaxDynamicSharedMemorySize, CS_R1);
    cudaFuncSetAttribute(conv_mma_f16<2, 128>, cudaFuncAttributeMaxDynamicSharedMemorySize, CS_R2);
    cudaFuncSetAttribute(conv_mma_f16<4, 64>,  cudaFuncAttributeMaxDynamicSharedMemorySize, CS_R4);
    cudaFuncSetAttribute(simmax_mma_f16, cudaFuncAttributeMaxDynamicSharedMemorySize, SIM_SMEM);

    const float* outputs = (const float*)d_in[0];
    const float* styles  = (const float*)d_in[1];
    const float* w[7];
    const float* bs[7];
    for (int i = 0; i < 7; i++) {
        w[i]  = (const float*)d_in[2 + 2 * i];
        bs[i] = (const float*)d_in[3 + 2 * i];
    }

    const int cfg[7][3] = {{64,3,1},{64,64,4},{128,64,4},{128,128,8},
                           {256,128,8},{256,256,16},{256,256,16}};
    const long woff[7] = {0, 4608, 23040, 59904, 133632, 281088, 576000};
    for (int i = 0; i < 7; i++) {
        int total = cfg[i][2] * cfg[i][0] * 72;
        wtrans_kernel<<<(total + 255) / 256, 256>>>(w[i], wH + woff[i], cfg[i][0], cfg[i][1], total);
    }

    run_stack(outputs, wH, bs, pad0, pad1, pad2, pad3, pad4, pad5, pad6, f1, f2, f3, xT);
    run_stack(styles,  wH, bs, pad0, pad1, pad2, pad3, pad4, pad5, pad6, f1, f2, f3, sT);

    initmax_kernel<<<(BATCH * FEATN + 255) / 256, 256>>>(gmax);
    simmax_mma_f16<<<dim3(FEATN / 128, FEATN / 128, BATCH), 256, SIM_SMEM>>>(xT, sT, gmax);
    final_loss_kernel<<<1, 256>>>(gmax, (float*)d_out);
}